// round 1
// baseline (speedup 1.0000x reference)
#include <cuda_runtime.h>

// Problem constants
#define BATCH 4
#define SEQ   2048
#define DMODEL 1024
#define NHEAD 16
#define DHEAD 64
#define MTOT  (BATCH * SEQ)   // 8192

// Scratch (device globals; no allocation allowed)
__device__ float g_q[BATCH * SEQ * DMODEL];
__device__ float g_k[BATCH * SEQ * DMODEL];
__device__ float g_v[BATCH * SEQ * DMODEL];
__device__ float g_o[BATCH * SEQ * DMODEL];

// ---------------------------------------------------------------------------
// GEMM: C[M,N] = A[M,K] * W[N,K]^T   (torch Linear), K = N = 1024
// BM=BN=64, BK=16, 256 threads, 4x4 register tile per thread
// ---------------------------------------------------------------------------
__global__ __launch_bounds__(256) void gemm_xwt(const float* __restrict__ A,
                                                const float* __restrict__ W,
                                                float* __restrict__ C)
{
    const int K = DMODEL, N = DMODEL;
    __shared__ float As[64][17];  // [m][k], pad to 17 (odd) -> conflict-free
    __shared__ float Ws[16][68];  // [k][n], pad 68 keeps float4 alignment

    const int tid = threadIdx.x;
    const int tx = tid & 15;      // 0..15 -> n
    const int ty = tid >> 4;      // 0..15 -> m
    const int m0 = blockIdx.x * 64;
    const int n0 = blockIdx.y * 64;

    float acc[4][4] = {};

    for (int k0 = 0; k0 < K; k0 += 16) {
        // Load A tile 64x16 (natural layout)
        {
            const int r  = tid >> 2;          // 0..63
            const int kq = (tid & 3) << 2;    // 0,4,8,12
            const float4 av = *(const float4*)(A + (size_t)(m0 + r) * K + k0 + kq);
            As[r][kq + 0] = av.x; As[r][kq + 1] = av.y;
            As[r][kq + 2] = av.z; As[r][kq + 3] = av.w;
        }
        // Load W tile 64x16, store transposed [k][n]
        {
            const int r  = tid >> 2;
            const int kq = (tid & 3) << 2;
            const float4 wv = *(const float4*)(W + (size_t)(n0 + r) * K + k0 + kq);
            Ws[kq + 0][r] = wv.x; Ws[kq + 1][r] = wv.y;
            Ws[kq + 2][r] = wv.z; Ws[kq + 3][r] = wv.w;
        }
        __syncthreads();

        #pragma unroll
        for (int kk = 0; kk < 16; kk++) {
            float a0 = As[ty * 4 + 0][kk];
            float a1 = As[ty * 4 + 1][kk];
            float a2 = As[ty * 4 + 2][kk];
            float a3 = As[ty * 4 + 3][kk];
            float4 bv = *(const float4*)&Ws[kk][tx * 4];
            acc[0][0] += a0 * bv.x; acc[0][1] += a0 * bv.y; acc[0][2] += a0 * bv.z; acc[0][3] += a0 * bv.w;
            acc[1][0] += a1 * bv.x; acc[1][1] += a1 * bv.y; acc[1][2] += a1 * bv.z; acc[1][3] += a1 * bv.w;
            acc[2][0] += a2 * bv.x; acc[2][1] += a2 * bv.y; acc[2][2] += a2 * bv.z; acc[2][3] += a2 * bv.w;
            acc[3][0] += a3 * bv.x; acc[3][1] += a3 * bv.y; acc[3][2] += a3 * bv.z; acc[3][3] += a3 * bv.w;
        }
        __syncthreads();
    }

    #pragma unroll
    for (int i = 0; i < 4; i++) {
        float4 out;
        out.x = acc[i][0]; out.y = acc[i][1]; out.z = acc[i][2]; out.w = acc[i][3];
        *(float4*)(C + (size_t)(m0 + ty * 4 + i) * N + n0 + tx * 4) = out;
    }
}

// ---------------------------------------------------------------------------
// Flash-style attention, fp32. One block: 64 q-rows of one (b,h).
// BQ=64, BKV=32, 256 threads. s-tile: 4x2/thread, out-tile: 4x4/thread.
// Row reduction across the 16 tx lanes via shfl_xor (lane = (ty&1)*16 + tx).
// ---------------------------------------------------------------------------
__global__ __launch_bounds__(256) void attn_kernel(const float* __restrict__ qp,
                                                   const float* __restrict__ kp,
                                                   const float* __restrict__ vp,
                                                   float* __restrict__ op)
{
    __shared__ float Qs[64][65];  // [d][q]   (pre-scaled by 1/8)
    __shared__ float Ks[64][33];  // [d][kv]
    __shared__ float Vs[32][68];  // [kv][d]  pad 68 -> float4-aligned rows
    __shared__ float Ps[64][33];  // [q][kv]

    const int tid = threadIdx.x;
    const int tx = tid & 15;
    const int ty = tid >> 4;

    const int bh = blockIdx.y;
    const int b  = bh / NHEAD;
    const int h  = bh % NHEAD;
    const int q0 = blockIdx.x * 64;

    const float* qb = qp + (size_t)b * SEQ * DMODEL + h * DHEAD;
    const float* kb = kp + (size_t)b * SEQ * DMODEL + h * DHEAD;
    const float* vb = vp + (size_t)b * SEQ * DMODEL + h * DHEAD;

    // Load Q tile transposed, pre-scaled by 1/sqrt(dk) = 1/8
    for (int idx = tid; idx < 64 * 64; idx += 256) {
        const int r = idx >> 6;   // q row
        const int c = idx & 63;   // d
        Qs[c][r] = 0.125f * qb[(size_t)(q0 + r) * DMODEL + c];
    }

    float m_i[4], l_i[4], accv[4][4];
    #pragma unroll
    for (int i = 0; i < 4; i++) {
        m_i[i] = -1e30f; l_i[i] = 0.f;
        #pragma unroll
        for (int j = 0; j < 4; j++) accv[i][j] = 0.f;
    }

    for (int kv0 = 0; kv0 < SEQ; kv0 += 32) {
        __syncthreads();   // protect Ks/Vs/Ps from previous iteration's readers
        for (int idx = tid; idx < 32 * 64; idx += 256) {
            const int r = idx >> 6;  // kv
            const int c = idx & 63;  // d
            Ks[c][r] = kb[(size_t)(kv0 + r) * DMODEL + c];
            Vs[r][c] = vb[(size_t)(kv0 + r) * DMODEL + c];
        }
        __syncthreads();

        // s = (Q/8) @ K^T : 4x2 per thread
        float s[4][2] = {};
        #pragma unroll
        for (int d = 0; d < 64; d++) {
            float qv0 = Qs[d][ty * 4 + 0];
            float qv1 = Qs[d][ty * 4 + 1];
            float qv2 = Qs[d][ty * 4 + 2];
            float qv3 = Qs[d][ty * 4 + 3];
            float k0 = Ks[d][tx * 2 + 0];
            float k1 = Ks[d][tx * 2 + 1];
            s[0][0] += qv0 * k0; s[0][1] += qv0 * k1;
            s[1][0] += qv1 * k0; s[1][1] += qv1 * k1;
            s[2][0] += qv2 * k0; s[2][1] += qv2 * k1;
            s[3][0] += qv3 * k0; s[3][1] += qv3 * k1;
        }

        // online softmax update (row reduction over 16 tx lanes)
        #pragma unroll
        for (int i = 0; i < 4; i++) {
            float t = fmaxf(s[i][0], s[i][1]);
            t = fmaxf(t, __shfl_xor_sync(0xffffffffu, t, 1));
            t = fmaxf(t, __shfl_xor_sync(0xffffffffu, t, 2));
            t = fmaxf(t, __shfl_xor_sync(0xffffffffu, t, 4));
            t = fmaxf(t, __shfl_xor_sync(0xffffffffu, t, 8));
            const float mnew = fmaxf(m_i[i], t);
            const float corr = __expf(m_i[i] - mnew);
            const float p0 = __expf(s[i][0] - mnew);
            const float p1 = __expf(s[i][1] - mnew);
            float rs = p0 + p1;
            rs += __shfl_xor_sync(0xffffffffu, rs, 1);
            rs += __shfl_xor_sync(0xffffffffu, rs, 2);
            rs += __shfl_xor_sync(0xffffffffu, rs, 4);
            rs += __shfl_xor_sync(0xffffffffu, rs, 8);
            l_i[i] = l_i[i] * corr + rs;
            m_i[i] = mnew;
            #pragma unroll
            for (int j = 0; j < 4; j++) accv[i][j] *= corr;
            Ps[ty * 4 + i][tx * 2 + 0] = p0;
            Ps[ty * 4 + i][tx * 2 + 1] = p1;
        }
        __syncthreads();

        // acc += P @ V : 4x4 per thread
        #pragma unroll
        for (int kk = 0; kk < 32; kk++) {
            float p0 = Ps[ty * 4 + 0][kk];
            float p1 = Ps[ty * 4 + 1][kk];
            float p2 = Ps[ty * 4 + 2][kk];
            float p3 = Ps[ty * 4 + 3][kk];
            float4 vv = *(const float4*)&Vs[kk][tx * 4];
            accv[0][0] += p0 * vv.x; accv[0][1] += p0 * vv.y; accv[0][2] += p0 * vv.z; accv[0][3] += p0 * vv.w;
            accv[1][0] += p1 * vv.x; accv[1][1] += p1 * vv.y; accv[1][2] += p1 * vv.z; accv[1][3] += p1 * vv.w;
            accv[2][0] += p2 * vv.x; accv[2][1] += p2 * vv.y; accv[2][2] += p2 * vv.z; accv[2][3] += p2 * vv.w;
            accv[3][0] += p3 * vv.x; accv[3][1] += p3 * vv.y; accv[3][2] += p3 * vv.z; accv[3][3] += p3 * vv.w;
        }
    }

    float* ob = op + (size_t)b * SEQ * DMODEL + h * DHEAD;
    #pragma unroll
    for (int i = 0; i < 4; i++) {
        const float inv_l = 1.0f / l_i[i];
        float4 out;
        out.x = accv[i][0] * inv_l;
        out.y = accv[i][1] * inv_l;
        out.z = accv[i][2] * inv_l;
        out.w = accv[i][3] * inv_l;
        *(float4*)(ob + (size_t)(q0 + ty * 4 + i) * DMODEL + tx * 4) = out;
    }
}

// ---------------------------------------------------------------------------
// Launch
// ---------------------------------------------------------------------------
extern "C" void kernel_launch(void* const* d_in, const int* in_sizes, int n_in,
                              void* d_out, int out_size)
{
    const float* Q  = (const float*)d_in[0];
    const float* K  = (const float*)d_in[1];
    const float* V  = (const float*)d_in[2];
    const float* WQ = (const float*)d_in[3];
    const float* WK = (const float*)d_in[4];
    const float* WV = (const float*)d_in[5];
    const float* WO = (const float*)d_in[6];
    float* out = (float*)d_out;

    float *gq, *gk, *gv, *go;
    cudaGetSymbolAddress((void**)&gq, g_q);
    cudaGetSymbolAddress((void**)&gk, g_k);
    cudaGetSymbolAddress((void**)&gv, g_v);
    cudaGetSymbolAddress((void**)&go, g_o);

    dim3 blk(256);
    dim3 gemm_grid(MTOT / 64, DMODEL / 64);   // 128 x 16

    gemm_xwt<<<gemm_grid, blk>>>(Q, WQ, gq);
    gemm_xwt<<<gemm_grid, blk>>>(K, WK, gk);
    gemm_xwt<<<gemm_grid, blk>>>(V, WV, gv);

    dim3 attn_grid(SEQ / 64, BATCH * NHEAD);  // 32 x 64
    attn_kernel<<<attn_grid, blk>>>(gq, gk, gv, go);

    gemm_xwt<<<gemm_grid, blk>>>(go, WO, out);
}

// round 2
// speedup vs baseline: 3.2540x; 3.2540x over previous
#include <cuda_runtime.h>

#define BATCH 4
#define SEQ   2048
#define DMODEL 1024
#define NHEAD 16
#define DHEAD 64
#define MTOT  (BATCH * SEQ)   // 8192

__device__ float g_q[BATCH * SEQ * DMODEL];
__device__ float g_k[BATCH * SEQ * DMODEL];
__device__ float g_v[BATCH * SEQ * DMODEL];
__device__ float g_o[BATCH * SEQ * DMODEL];

// ---- tf32 helpers ---------------------------------------------------------
__device__ __forceinline__ float tf32r(float x) {
    unsigned r;
    asm("cvt.rna.tf32.f32 %0, %1;" : "=r"(r) : "f"(x));
    return __uint_as_float(r);
}
__device__ __forceinline__ unsigned fbits(float x) { return __float_as_uint(x); }

__device__ __forceinline__ void mma_tf32(float c[4], const unsigned a[4], const unsigned b[2]) {
    asm volatile(
        "mma.sync.aligned.m16n8k8.row.col.f32.tf32.tf32.f32 "
        "{%0,%1,%2,%3}, {%4,%5,%6,%7}, {%8,%9}, {%0,%1,%2,%3};"
        : "+f"(c[0]), "+f"(c[1]), "+f"(c[2]), "+f"(c[3])
        : "r"(a[0]), "r"(a[1]), "r"(a[2]), "r"(a[3]), "r"(b[0]), "r"(b[1]));
}

// ---------------------------------------------------------------------------
// GEMM: C[M,1024] = A[M,1024] @ W[1024,1024]^T  (torch Linear)
// block 128x128, BK=16 double-buffered, 256 threads (8 warps), warp 32x64
// ---------------------------------------------------------------------------
#define PK 20   // BK=16 padded to 20 floats: conflict-free fragment reads

__global__ __launch_bounds__(256, 2) void gemm_tc(const float* __restrict__ A,
                                                  const float* __restrict__ W,
                                                  float* __restrict__ C)
{
    __shared__ float As[2][128][PK];
    __shared__ float Bs[2][128][PK];

    const int tid  = threadIdx.x;
    const int lane = tid & 31;
    const int wid  = tid >> 5;
    const int wm   = (wid >> 1) * 32;   // warp m offset (4 warp-rows)
    const int wn   = (wid & 1) * 64;    // warp n offset (2 warp-cols)
    const int m0   = blockIdx.x * 128;
    const int n0   = blockIdx.y * 128;
    const int g    = lane >> 2;         // 0..7
    const int q4   = lane & 3;          // 0..3

    float acc[2][8][4] = {};

    // stage loader: 128 rows x 16 cols for A and W, tf32-rounded
    auto load_stage = [&](int k0, int buf) {
        #pragma unroll
        for (int i = 0; i < 2; i++) {
            const int idx = tid + i * 256;          // 0..511
            const int r = idx >> 2;                 // 0..127
            const int q = (idx & 3) * 4;
            float4 av = *(const float4*)(A + (size_t)(m0 + r) * 1024 + k0 + q);
            As[buf][r][q + 0] = tf32r(av.x); As[buf][r][q + 1] = tf32r(av.y);
            As[buf][r][q + 2] = tf32r(av.z); As[buf][r][q + 3] = tf32r(av.w);
            float4 wv = *(const float4*)(W + (size_t)(n0 + r) * 1024 + k0 + q);
            Bs[buf][r][q + 0] = tf32r(wv.x); Bs[buf][r][q + 1] = tf32r(wv.y);
            Bs[buf][r][q + 2] = tf32r(wv.z); Bs[buf][r][q + 3] = tf32r(wv.w);
        }
    };

    load_stage(0, 0);
    __syncthreads();

    for (int s = 0; s < 64; s++) {
        const int buf = s & 1;
        if (s + 1 < 64) load_stage((s + 1) * 16, buf ^ 1);

        #pragma unroll
        for (int ks = 0; ks < 2; ks++) {
            const int k = ks * 8;
            unsigned a[2][4];
            #pragma unroll
            for (int i = 0; i < 2; i++) {
                const int r = wm + 16 * i + g;
                a[i][0] = fbits(As[buf][r    ][k + q4]);
                a[i][1] = fbits(As[buf][r + 8][k + q4]);
                a[i][2] = fbits(As[buf][r    ][k + q4 + 4]);
                a[i][3] = fbits(As[buf][r + 8][k + q4 + 4]);
            }
            #pragma unroll
            for (int j = 0; j < 8; j++) {
                unsigned b[2];
                const int n = wn + 8 * j + g;
                b[0] = fbits(Bs[buf][n][k + q4]);
                b[1] = fbits(Bs[buf][n][k + q4 + 4]);
                mma_tf32(acc[0][j], a[0], b);
                mma_tf32(acc[1][j], a[1], b);
            }
        }
        __syncthreads();
    }

    #pragma unroll
    for (int i = 0; i < 2; i++) {
        #pragma unroll
        for (int j = 0; j < 8; j++) {
            const int r = m0 + wm + 16 * i + g;
            const int c = n0 + wn + 8 * j + 2 * q4;
            float2 v0; v0.x = acc[i][j][0]; v0.y = acc[i][j][1];
            float2 v1; v1.x = acc[i][j][2]; v1.y = acc[i][j][3];
            *(float2*)(C + (size_t)r * 1024 + c)       = v0;
            *(float2*)(C + (size_t)(r + 8) * 1024 + c) = v1;
        }
    }
}

// ---------------------------------------------------------------------------
// Flash attention, tf32 mma. Block = 64 q-rows of one (b,h), 128 threads
// (4 warps, 16 q-rows each). BKV=32 per iteration.
// ---------------------------------------------------------------------------
__global__ __launch_bounds__(128) void attn_tc(const float* __restrict__ qp,
                                               const float* __restrict__ kp,
                                               const float* __restrict__ vp,
                                               float* __restrict__ op)
{
    __shared__ float Qs[64][68];  // [q][d]   tf32, pre-scaled by 1/8
    __shared__ float Ks[32][68];  // [kv][d]  tf32
    __shared__ float Vs[32][72];  // [kv][d]  tf32
    __shared__ float Ps[64][36];  // [q][kv]  tf32

    const int tid  = threadIdx.x;
    const int lane = tid & 31;
    const int wid  = tid >> 5;
    const int g    = lane >> 2;
    const int q4   = lane & 3;
    const int qw   = wid * 16;    // warp's q-row band

    const int bh = blockIdx.y;
    const int b  = bh / NHEAD;
    const int h  = bh % NHEAD;
    const int q0 = blockIdx.x * 64;

    const float* qb = qp + (size_t)b * SEQ * DMODEL + h * DHEAD;
    const float* kb = kp + (size_t)b * SEQ * DMODEL + h * DHEAD;
    const float* vb = vp + (size_t)b * SEQ * DMODEL + h * DHEAD;

    // load Q (64x64), scaled + tf32
    #pragma unroll
    for (int i = 0; i < 8; i++) {
        const int idx = tid + i * 128;      // 0..1023
        const int r = idx >> 4;
        const int c = (idx & 15) * 4;
        float4 v = *(const float4*)(qb + (size_t)(q0 + r) * DMODEL + c);
        Qs[r][c + 0] = tf32r(0.125f * v.x);
        Qs[r][c + 1] = tf32r(0.125f * v.y);
        Qs[r][c + 2] = tf32r(0.125f * v.z);
        Qs[r][c + 3] = tf32r(0.125f * v.w);
    }

    float m_i[2] = {-1e30f, -1e30f};
    float l_i[2] = {0.f, 0.f};
    float oac[8][4] = {};

    for (int kv0 = 0; kv0 < SEQ; kv0 += 32) {
        __syncthreads();
        #pragma unroll
        for (int i = 0; i < 4; i++) {
            const int idx = tid + i * 128;  // 0..511
            const int r = idx >> 4;
            const int c = (idx & 15) * 4;
            float4 kv = *(const float4*)(kb + (size_t)(kv0 + r) * DMODEL + c);
            Ks[r][c + 0] = tf32r(kv.x); Ks[r][c + 1] = tf32r(kv.y);
            Ks[r][c + 2] = tf32r(kv.z); Ks[r][c + 3] = tf32r(kv.w);
            float4 vv = *(const float4*)(vb + (size_t)(kv0 + r) * DMODEL + c);
            Vs[r][c + 0] = tf32r(vv.x); Vs[r][c + 1] = tf32r(vv.y);
            Vs[r][c + 2] = tf32r(vv.z); Vs[r][c + 3] = tf32r(vv.w);
        }
        __syncthreads();

        // S = (Q/8) @ K^T : 4 kv-tiles (n8), 8 k-steps over d
        float sa[4][4] = {};
        #pragma unroll
        for (int ks = 0; ks < 8; ks++) {
            const int k = ks * 8;
            unsigned a[4];
            a[0] = fbits(Qs[qw + g    ][k + q4]);
            a[1] = fbits(Qs[qw + g + 8][k + q4]);
            a[2] = fbits(Qs[qw + g    ][k + q4 + 4]);
            a[3] = fbits(Qs[qw + g + 8][k + q4 + 4]);
            #pragma unroll
            for (int nt = 0; nt < 4; nt++) {
                unsigned bfr[2];
                bfr[0] = fbits(Ks[8 * nt + g][k + q4]);
                bfr[1] = fbits(Ks[8 * nt + g][k + q4 + 4]);
                mma_tf32(sa[nt], a, bfr);
            }
        }

        // online softmax for rows (qw+g) and (qw+g+8)
        float mx0 = -1e30f, mx1 = -1e30f;
        #pragma unroll
        for (int nt = 0; nt < 4; nt++) {
            mx0 = fmaxf(mx0, fmaxf(sa[nt][0], sa[nt][1]));
            mx1 = fmaxf(mx1, fmaxf(sa[nt][2], sa[nt][3]));
        }
        mx0 = fmaxf(mx0, __shfl_xor_sync(0xffffffffu, mx0, 1));
        mx0 = fmaxf(mx0, __shfl_xor_sync(0xffffffffu, mx0, 2));
        mx1 = fmaxf(mx1, __shfl_xor_sync(0xffffffffu, mx1, 1));
        mx1 = fmaxf(mx1, __shfl_xor_sync(0xffffffffu, mx1, 2));

        const float mn0 = fmaxf(m_i[0], mx0);
        const float mn1 = fmaxf(m_i[1], mx1);
        const float corr0 = __expf(m_i[0] - mn0);
        const float corr1 = __expf(m_i[1] - mn1);

        float rs0 = 0.f, rs1 = 0.f;
        #pragma unroll
        for (int nt = 0; nt < 4; nt++) {
            const float p00 = __expf(sa[nt][0] - mn0);
            const float p01 = __expf(sa[nt][1] - mn0);
            const float p10 = __expf(sa[nt][2] - mn1);
            const float p11 = __expf(sa[nt][3] - mn1);
            rs0 += p00 + p01;
            rs1 += p10 + p11;
            const int c = 8 * nt + 2 * q4;
            Ps[qw + g    ][c]     = tf32r(p00);
            Ps[qw + g    ][c + 1] = tf32r(p01);
            Ps[qw + g + 8][c]     = tf32r(p10);
            Ps[qw + g + 8][c + 1] = tf32r(p11);
        }
        rs0 += __shfl_xor_sync(0xffffffffu, rs0, 1);
        rs0 += __shfl_xor_sync(0xffffffffu, rs0, 2);
        rs1 += __shfl_xor_sync(0xffffffffu, rs1, 1);
        rs1 += __shfl_xor_sync(0xffffffffu, rs1, 2);

        l_i[0] = l_i[0] * corr0 + rs0;  m_i[0] = mn0;
        l_i[1] = l_i[1] * corr1 + rs1;  m_i[1] = mn1;

        #pragma unroll
        for (int j = 0; j < 8; j++) {
            oac[j][0] *= corr0; oac[j][1] *= corr0;
            oac[j][2] *= corr1; oac[j][3] *= corr1;
        }
        __syncwarp();

        // O += P @ V : 8 d-tiles (n8), 4 k-steps over kv
        #pragma unroll
        for (int ks = 0; ks < 4; ks++) {
            const int k = ks * 8;
            unsigned a[4];
            a[0] = fbits(Ps[qw + g    ][k + q4]);
            a[1] = fbits(Ps[qw + g + 8][k + q4]);
            a[2] = fbits(Ps[qw + g    ][k + q4 + 4]);
            a[3] = fbits(Ps[qw + g + 8][k + q4 + 4]);
            #pragma unroll
            for (int j = 0; j < 8; j++) {
                unsigned bfr[2];
                bfr[0] = fbits(Vs[k + q4    ][8 * j + g]);
                bfr[1] = fbits(Vs[k + q4 + 4][8 * j + g]);
                mma_tf32(oac[j], a, bfr);
            }
        }
    }

    // epilogue
    float* ob = op + (size_t)b * SEQ * DMODEL + h * DHEAD;
    const float inv0 = 1.0f / l_i[0];
    const float inv1 = 1.0f / l_i[1];
    #pragma unroll
    for (int j = 0; j < 8; j++) {
        const int r = q0 + qw + g;
        const int c = 8 * j + 2 * q4;
        float2 v0; v0.x = oac[j][0] * inv0; v0.y = oac[j][1] * inv0;
        float2 v1; v1.x = oac[j][2] * inv1; v1.y = oac[j][3] * inv1;
        *(float2*)(ob + (size_t)r * DMODEL + c)       = v0;
        *(float2*)(ob + (size_t)(r + 8) * DMODEL + c) = v1;
    }
}

// ---------------------------------------------------------------------------
extern "C" void kernel_launch(void* const* d_in, const int* in_sizes, int n_in,
                              void* d_out, int out_size)
{
    const float* Q  = (const float*)d_in[0];
    const float* K  = (const float*)d_in[1];
    const float* V  = (const float*)d_in[2];
    const float* WQ = (const float*)d_in[3];
    const float* WK = (const float*)d_in[4];
    const float* WV = (const float*)d_in[5];
    const float* WO = (const float*)d_in[6];
    float* out = (float*)d_out;

    float *gq, *gk, *gv, *go;
    cudaGetSymbolAddress((void**)&gq, g_q);
    cudaGetSymbolAddress((void**)&gk, g_k);
    cudaGetSymbolAddress((void**)&gv, g_v);
    cudaGetSymbolAddress((void**)&go, g_o);

    dim3 gemm_grid(MTOT / 128, DMODEL / 128);   // 64 x 8
    gemm_tc<<<gemm_grid, 256>>>(Q, WQ, gq);
    gemm_tc<<<gemm_grid, 256>>>(K, WK, gk);
    gemm_tc<<<gemm_grid, 256>>>(V, WV, gv);

    dim3 attn_grid(SEQ / 64, BATCH * NHEAD);    // 32 x 64
    attn_tc<<<attn_grid, 128>>>(gq, gk, gv, go);

    gemm_tc<<<gemm_grid, 256>>>(go, WO, out);
}

// round 4
// speedup vs baseline: 4.3102x; 1.3246x over previous
#include <cuda_runtime.h>
#include <cstdint>

#define BATCH 4
#define SEQ   2048
#define DMODEL 1024
#define NHEAD 16
#define DHEAD 64
#define MTOT  (BATCH * SEQ)   // 8192

__device__ float g_q[BATCH * SEQ * DMODEL];
__device__ float g_k[BATCH * SEQ * DMODEL];
__device__ float g_v[BATCH * SEQ * DMODEL];
__device__ float g_o[BATCH * SEQ * DMODEL];

// ---------------- helpers --------------------------------------------------
__device__ __forceinline__ uint32_t smem_u32(const void* p) {
    uint32_t a;
    asm("{ .reg .u64 t; cvta.to.shared.u64 t, %1; cvt.u32.u64 %0, t; }" : "=r"(a) : "l"(p));
    return a;
}
__device__ __forceinline__ float tf32r(float x) {
    unsigned r; asm("cvt.rna.tf32.f32 %0, %1;" : "=r"(r) : "f"(x));
    return __uint_as_float(r);
}
__device__ __forceinline__ float4 tf32x4(float4 v) {
    float4 t; t.x = tf32r(v.x); t.y = tf32r(v.y); t.z = tf32r(v.z); t.w = tf32r(v.w);
    return t;
}
__device__ __forceinline__ void ldsm4(uint32_t r[4], uint32_t addr) {
    asm volatile("ldmatrix.sync.aligned.m8n8.x4.shared.b16 {%0,%1,%2,%3}, [%4];"
                 : "=r"(r[0]), "=r"(r[1]), "=r"(r[2]), "=r"(r[3]) : "r"(addr) : "memory");
}
__device__ __forceinline__ void mma_tf32(float c[4], const uint32_t a[4], const uint32_t b[2]) {
    asm volatile(
        "mma.sync.aligned.m16n8k8.row.col.f32.tf32.tf32.f32 "
        "{%0,%1,%2,%3}, {%4,%5,%6,%7}, {%8,%9}, {%0,%1,%2,%3};"
        : "+f"(c[0]), "+f"(c[1]), "+f"(c[2]), "+f"(c[3])
        : "r"(a[0]), "r"(a[1]), "r"(a[2]), "r"(a[3]), "r"(b[0]), "r"(b[1]));
}
// lane byte-offsets for ldmatrix fragment tiles (strideB = row stride in bytes)
// A-type (m16 x k8):  t0=(r0..7,klo) t1=(r8..15,klo) t2=(r0..7,khi) t3=(r8..15,khi)
__device__ __forceinline__ uint32_t ldsmA_off(int lane, int strideB) {
    const int r = lane & 7, t = lane >> 3;
    return (uint32_t)((r + (t & 1) * 8) * strideB + (t >> 1) * 16);
}
// B-type (2 n-tiles x k8): t0=(n0..7,klo) t1=(n0..7,khi) t2=(n8..15,klo) t3=(n8..15,khi)
__device__ __forceinline__ uint32_t ldsmB_off(int lane, int strideB) {
    const int r = lane & 7, t = lane >> 3;
    return (uint32_t)((r + (t >> 1) * 8) * strideB + (t & 1) * 16);
}

// ===========================================================================
// GEMM: C[M,1024] = A[M,1024] @ W[1024,1024]^T
// block 128x128, 128 threads (4 warps, 64x64 warp tile), BK=16 pipelined
// ===========================================================================
#define GSTR  20            // floats per smem row (80B = 5x16B, odd -> ldsm ok)
#define GSTRB 80
#define GSTAGE (128 * GSTRB)

struct GemmSmem {
    float As[2][128][GSTR];
    float Bs[2][128][GSTR];
};

__device__ __forceinline__ void gemm_body(const float* __restrict__ A,
                                          const float* __restrict__ W,
                                          float* __restrict__ C,
                                          int m0, int n0)
{
    __shared__ GemmSmem sm;
    const int tid  = threadIdx.x;
    const int lane = tid & 31;
    const int wid  = tid >> 5;
    const int wm   = (wid >> 1) * 64;
    const int wn   = (wid & 1) * 64;

    const uint32_t asb = smem_u32(&sm.As[0][0][0]);
    const uint32_t bsb = smem_u32(&sm.Bs[0][0][0]);
    const uint32_t aoff = ldsmA_off(lane, GSTRB);
    const uint32_t boff = ldsmB_off(lane, GSTRB);

    float acc[4][8][4] = {};
    float4 pa[4], pw[4];

    auto ldg = [&](int k0) {
        #pragma unroll
        for (int i = 0; i < 4; i++) {
            const int slot = tid + 128 * i;
            const int r = slot >> 2, q = (slot & 3) * 4;
            pa[i] = *(const float4*)(A + (size_t)(m0 + r) * 1024 + k0 + q);
            pw[i] = *(const float4*)(W + (size_t)(n0 + r) * 1024 + k0 + q);
        }
    };
    auto sts = [&](int buf) {
        #pragma unroll
        for (int i = 0; i < 4; i++) {
            const int slot = tid + 128 * i;
            const int r = slot >> 2, q = (slot & 3) * 4;
            *(float4*)&sm.As[buf][r][q] = tf32x4(pa[i]);
            *(float4*)&sm.Bs[buf][r][q] = tf32x4(pw[i]);
        }
    };

    ldg(0);
    sts(0);
    __syncthreads();

    for (int s = 0; s < 64; s++) {
        const int buf = s & 1;
        if (s + 1 < 64) ldg((s + 1) * 16);

        #pragma unroll
        for (int ks = 0; ks < 2; ks++) {
            uint32_t a[4][4], b[4][4];
            #pragma unroll
            for (int i = 0; i < 4; i++)
                ldsm4(a[i], asb + buf * GSTAGE + (wm + 16 * i) * GSTRB + ks * 32 + aoff);
            #pragma unroll
            for (int p = 0; p < 4; p++)
                ldsm4(b[p], bsb + buf * GSTAGE + (wn + 16 * p) * GSTRB + ks * 32 + boff);
            #pragma unroll
            for (int i = 0; i < 4; i++)
                #pragma unroll
                for (int j = 0; j < 8; j++)
                    mma_tf32(acc[i][j], a[i], &b[j >> 1][(j & 1) * 2]);
        }
        if (s + 1 < 64) sts(buf ^ 1);
        __syncthreads();
    }

    const int g = lane >> 2, q4 = lane & 3;
    #pragma unroll
    for (int i = 0; i < 4; i++)
        #pragma unroll
        for (int j = 0; j < 8; j++) {
            const int row = m0 + wm + 16 * i + g;
            const int col = n0 + wn + 8 * j + 2 * q4;
            float2 v0; v0.x = acc[i][j][0]; v0.y = acc[i][j][1];
            float2 v1; v1.x = acc[i][j][2]; v1.y = acc[i][j][3];
            *(float2*)(C + (size_t)row * 1024 + col)       = v0;
            *(float2*)(C + (size_t)(row + 8) * 1024 + col) = v1;
        }
}

__global__ __launch_bounds__(128) void gemm_tc(const float* __restrict__ A,
                                               const float* __restrict__ W,
                                               float* __restrict__ C)
{
    gemm_body(A, W, C, blockIdx.x * 128, blockIdx.y * 128);
}

__global__ __launch_bounds__(128) void gemm_qkv(const float* __restrict__ Q,
                                                const float* __restrict__ K,
                                                const float* __restrict__ V,
                                                const float* __restrict__ WQ,
                                                const float* __restrict__ WK,
                                                const float* __restrict__ WV,
                                                float* __restrict__ gq,
                                                float* __restrict__ gk,
                                                float* __restrict__ gv)
{
    const float* A;
    const float* W;
    float* C;
    if (blockIdx.z == 0)      { A = Q; W = WQ; C = gq; }
    else if (blockIdx.z == 1) { A = K; W = WK; C = gk; }
    else                      { A = V; W = WV; C = gv; }
    gemm_body(A, W, C, blockIdx.x * 128, blockIdx.y * 128);
}

// ===========================================================================
// Flash attention: BQ=128 (4 warps x 32 q-rows), BKV=32, tf32 mma + ldmatrix
// smem: Qs[128][68], Ks[32][68], Vt[64][36], Ps[128][36]  (71168 B dynamic)
// ===========================================================================
#define QS_STR 68
#define KS_STR 68
#define VT_STR 36
#define PS_STR 36
#define OFF_KS 8704
#define OFF_VT 10880
#define OFF_PS 13184
#define ATTN_SMEM 71168

__global__ __launch_bounds__(128) void attn_tc(const float* __restrict__ qp,
                                               const float* __restrict__ kp,
                                               const float* __restrict__ vp,
                                               float* __restrict__ op)
{
    extern __shared__ float sm[];
    float* Qs = sm;
    float* Ks = sm + OFF_KS;
    float* Vt = sm + OFF_VT;
    float* Ps = sm + OFF_PS;
    const uint32_t qsb = smem_u32(Qs);
    const uint32_t ksb = smem_u32(Ks);
    const uint32_t vtb = smem_u32(Vt);
    const uint32_t psb = smem_u32(Ps);

    const int tid  = threadIdx.x;
    const int lane = tid & 31;
    const int wid  = tid >> 5;
    const int g    = lane >> 2;
    const int q4   = lane & 3;
    const int qw   = wid * 32;

    const uint32_t aoffQ = ldsmA_off(lane, QS_STR * 4);
    const uint32_t boffK = ldsmB_off(lane, KS_STR * 4);
    const uint32_t aoffP = ldsmA_off(lane, PS_STR * 4);
    const uint32_t boffV = ldsmB_off(lane, VT_STR * 4);

    const int bh = blockIdx.y;
    const int b  = bh / NHEAD;
    const int h  = bh % NHEAD;
    const int q0 = blockIdx.x * 128;

    const float* qb = qp + (size_t)b * SEQ * DMODEL + h * DHEAD;
    const float* kb = kp + (size_t)b * SEQ * DMODEL + h * DHEAD;
    const float* vb = vp + (size_t)b * SEQ * DMODEL + h * DHEAD;

    const float QSCALE = 0.125f * 1.44269504088896340736f;  // (1/8)*log2(e)

    // stage Q (128x64), scaled + tf32
    #pragma unroll
    for (int i = 0; i < 16; i++) {
        const int slot = tid + 128 * i;
        const int r = slot >> 4, c = (slot & 15) * 4;
        float4 v = *(const float4*)(qb + (size_t)(q0 + r) * DMODEL + c);
        float4 t; t.x = tf32r(QSCALE * v.x); t.y = tf32r(QSCALE * v.y);
        t.z = tf32r(QSCALE * v.z); t.w = tf32r(QSCALE * v.w);
        *(float4*)&Qs[r * QS_STR + c] = t;
    }

    float m_i[2][2], l_i[2][2], oac[2][8][4];
    #pragma unroll
    for (int hh = 0; hh < 2; hh++) {
        m_i[hh][0] = m_i[hh][1] = -1e30f;
        l_i[hh][0] = l_i[hh][1] = 0.f;
        #pragma unroll
        for (int j = 0; j < 8; j++)
            oac[hh][j][0] = oac[hh][j][1] = oac[hh][j][2] = oac[hh][j][3] = 0.f;
    }

    for (int kv0 = 0; kv0 < SEQ; kv0 += 32) {
        __syncthreads();
        // stage K (32x64) row-major
        #pragma unroll
        for (int i = 0; i < 4; i++) {
            const int slot = tid + 128 * i;
            const int r = slot >> 4, c = (slot & 15) * 4;
            float4 v = *(const float4*)(kb + (size_t)(kv0 + r) * DMODEL + c);
            *(float4*)&Ks[r * KS_STR + c] = tf32x4(v);
        }
        // stage V transposed: Vt[d][kv]
        #pragma unroll
        for (int i = 0; i < 4; i++) {
            const int slot = tid + 128 * i;
            const int d = slot & 63, qd = slot >> 6;
            float4 t;
            t.x = tf32r(vb[(size_t)(kv0 + 4 * qd + 0) * DMODEL + d]);
            t.y = tf32r(vb[(size_t)(kv0 + 4 * qd + 1) * DMODEL + d]);
            t.z = tf32r(vb[(size_t)(kv0 + 4 * qd + 2) * DMODEL + d]);
            t.w = tf32r(vb[(size_t)(kv0 + 4 * qd + 3) * DMODEL + d]);
            *(float4*)&Vt[d * VT_STR + 4 * qd] = t;
        }
        __syncthreads();

        // ---- S = (Q*scale) @ K^T -------------------------------------
        float sa[2][4][4] = {};
        #pragma unroll
        for (int ks = 0; ks < 8; ks++) {
            uint32_t af[2][4], bf[2][4];
            #pragma unroll
            for (int hh = 0; hh < 2; hh++)
                ldsm4(af[hh], qsb + (qw + 16 * hh) * (QS_STR * 4) + ks * 32 + aoffQ);
            #pragma unroll
            for (int p = 0; p < 2; p++)
                ldsm4(bf[p], ksb + 16 * p * (KS_STR * 4) + ks * 32 + boffK);
            #pragma unroll
            for (int hh = 0; hh < 2; hh++)
                #pragma unroll
                for (int nt = 0; nt < 4; nt++)
                    mma_tf32(sa[hh][nt], af[hh], &bf[nt >> 1][(nt & 1) * 2]);
        }

        // ---- online softmax ------------------------------------------
        #pragma unroll
        for (int hh = 0; hh < 2; hh++) {
            float mx0 = -1e30f, mx1 = -1e30f;
            #pragma unroll
            for (int nt = 0; nt < 4; nt++) {
                mx0 = fmaxf(mx0, fmaxf(sa[hh][nt][0], sa[hh][nt][1]));
                mx1 = fmaxf(mx1, fmaxf(sa[hh][nt][2], sa[hh][nt][3]));
            }
            mx0 = fmaxf(mx0, __shfl_xor_sync(0xffffffffu, mx0, 1));
            mx0 = fmaxf(mx0, __shfl_xor_sync(0xffffffffu, mx0, 2));
            mx1 = fmaxf(mx1, __shfl_xor_sync(0xffffffffu, mx1, 1));
            mx1 = fmaxf(mx1, __shfl_xor_sync(0xffffffffu, mx1, 2));

            const float mn0 = fmaxf(m_i[hh][0], mx0);
            const float mn1 = fmaxf(m_i[hh][1], mx1);
            const float corr0 = exp2f(m_i[hh][0] - mn0);
            const float corr1 = exp2f(m_i[hh][1] - mn1);

            const int r0 = qw + 16 * hh + g;
            float rs0 = 0.f, rs1 = 0.f;
            #pragma unroll
            for (int nt = 0; nt < 4; nt++) {
                const float p00 = exp2f(sa[hh][nt][0] - mn0);
                const float p01 = exp2f(sa[hh][nt][1] - mn0);
                const float p10 = exp2f(sa[hh][nt][2] - mn1);
                const float p11 = exp2f(sa[hh][nt][3] - mn1);
                rs0 += p00 + p01;
                rs1 += p10 + p11;
                const int c = 8 * nt + 2 * q4;
                float2 lo; lo.x = tf32r(p00); lo.y = tf32r(p01);
                float2 hi; hi.x = tf32r(p10); hi.y = tf32r(p11);
                *(float2*)&Ps[r0 * PS_STR + c]       = lo;
                *(float2*)&Ps[(r0 + 8) * PS_STR + c] = hi;
            }
            rs0 += __shfl_xor_sync(0xffffffffu, rs0, 1);
            rs0 += __shfl_xor_sync(0xffffffffu, rs0, 2);
            rs1 += __shfl_xor_sync(0xffffffffu, rs1, 1);
            rs1 += __shfl_xor_sync(0xffffffffu, rs1, 2);

            l_i[hh][0] = l_i[hh][0] * corr0 + rs0;  m_i[hh][0] = mn0;
            l_i[hh][1] = l_i[hh][1] * corr1 + rs1;  m_i[hh][1] = mn1;

            #pragma unroll
            for (int j = 0; j < 8; j++) {
                oac[hh][j][0] *= corr0; oac[hh][j][1] *= corr0;
                oac[hh][j][2] *= corr1; oac[hh][j][3] *= corr1;
            }
        }
        __syncwarp();

        // ---- O += P @ V ----------------------------------------------
        #pragma unroll
        for (int ks = 0; ks < 4; ks++) {
            uint32_t af[2][4], vf[4][4];
            #pragma unroll
            for (int hh = 0; hh < 2; hh++)
                ldsm4(af[hh], psb + (qw + 16 * hh) * (PS_STR * 4) + ks * 32 + aoffP);
            #pragma unroll
            for (int p = 0; p < 4; p++)
                ldsm4(vf[p], vtb + 16 * p * (VT_STR * 4) + ks * 32 + boffV);
            #pragma unroll
            for (int hh = 0; hh < 2; hh++)
                #pragma unroll
                for (int j = 0; j < 8; j++)
                    mma_tf32(oac[hh][j], af[hh], &vf[j >> 1][(j & 1) * 2]);
        }
    }

    // epilogue
    float* ob = op + (size_t)b * SEQ * DMODEL + h * DHEAD;
    #pragma unroll
    for (int hh = 0; hh < 2; hh++) {
        const float inv0 = 1.0f / l_i[hh][0];
        const float inv1 = 1.0f / l_i[hh][1];
        const int r0 = q0 + qw + 16 * hh + g;
        #pragma unroll
        for (int j = 0; j < 8; j++) {
            const int c = 8 * j + 2 * q4;
            float2 v0; v0.x = oac[hh][j][0] * inv0; v0.y = oac[hh][j][1] * inv0;
            float2 v1; v1.x = oac[hh][j][2] * inv1; v1.y = oac[hh][j][3] * inv1;
            *(float2*)(ob + (size_t)r0 * DMODEL + c)       = v0;
            *(float2*)(ob + (size_t)(r0 + 8) * DMODEL + c) = v1;
        }
    }
}

// ===========================================================================
extern "C" void kernel_launch(void* const* d_in, const int* in_sizes, int n_in,
                              void* d_out, int out_size)
{
    const float* Q  = (const float*)d_in[0];
    const float* K  = (const float*)d_in[1];
    const float* V  = (const float*)d_in[2];
    const float* WQ = (const float*)d_in[3];
    const float* WK = (const float*)d_in[4];
    const float* WV = (const float*)d_in[5];
    const float* WO = (const float*)d_in[6];
    float* out = (float*)d_out;

    float *gq, *gk, *gv, *go;
    cudaGetSymbolAddress((void**)&gq, g_q);
    cudaGetSymbolAddress((void**)&gk, g_k);
    cudaGetSymbolAddress((void**)&gv, g_v);
    cudaGetSymbolAddress((void**)&go, g_o);

    static int init = 0;
    if (!init) {
        cudaFuncSetAttribute(attn_tc, cudaFuncAttributeMaxDynamicSharedMemorySize, ATTN_SMEM);
        init = 1;
    }

    dim3 qkv_grid(MTOT / 128, DMODEL / 128, 3);   // 64 x 8 x 3
    gemm_qkv<<<qkv_grid, 128>>>(Q, K, V, WQ, WK, WV, gq, gk, gv);

    dim3 attn_grid(SEQ / 128, BATCH * NHEAD);     // 16 x 64
    attn_tc<<<attn_grid, 128, ATTN_SMEM>>>(gq, gk, gv, go);

    dim3 gemm_grid(MTOT / 128, DMODEL / 128);     // 64 x 8
    gemm_tc<<<gemm_grid, 128>>>(go, WO, out);
}

// round 5
// speedup vs baseline: 4.4214x; 1.0258x over previous
#include <cuda_runtime.h>
#include <cstdint>

#define BATCH 4
#define SEQ   2048
#define DMODEL 1024
#define NHEAD 16
#define DHEAD 64
#define MTOT  (BATCH * SEQ)   // 8192

// projected intermediates
__device__ float g_q[BATCH * SEQ * DMODEL];
__device__ float g_k[BATCH * SEQ * DMODEL];
__device__ float g_v[BATCH * SEQ * DMODEL];
__device__ float g_o[BATCH * SEQ * DMODEL];
// tf32-rounded copies of inputs
__device__ float g_qr[BATCH * SEQ * DMODEL];
__device__ float g_kr[BATCH * SEQ * DMODEL];
__device__ float g_vr[BATCH * SEQ * DMODEL];
__device__ float g_wq[DMODEL * DMODEL];
__device__ float g_wk[DMODEL * DMODEL];
__device__ float g_wv[DMODEL * DMODEL];
__device__ float g_wo[DMODEL * DMODEL];

// ---------------- helpers --------------------------------------------------
__device__ __forceinline__ uint32_t smem_u32(const void* p) {
    uint32_t a;
    asm("{ .reg .u64 t; cvta.to.shared.u64 t, %1; cvt.u32.u64 %0, t; }" : "=r"(a) : "l"(p));
    return a;
}
__device__ __forceinline__ float tf32r(float x) {
    unsigned r; asm("cvt.rna.tf32.f32 %0, %1;" : "=r"(r) : "f"(x));
    return __uint_as_float(r);
}
__device__ __forceinline__ float4 tf32x4(float4 v) {
    float4 t; t.x = tf32r(v.x); t.y = tf32r(v.y); t.z = tf32r(v.z); t.w = tf32r(v.w);
    return t;
}
__device__ __forceinline__ unsigned fbits(float x) { return __float_as_uint(x); }

__device__ __forceinline__ void ldsm4(uint32_t r[4], uint32_t addr) {
    asm volatile("ldmatrix.sync.aligned.m8n8.x4.shared.b16 {%0,%1,%2,%3}, [%4];"
                 : "=r"(r[0]), "=r"(r[1]), "=r"(r[2]), "=r"(r[3]) : "r"(addr) : "memory");
}
__device__ __forceinline__ void mma_tf32(float c[4], const uint32_t a[4], const uint32_t b[2]) {
    asm volatile(
        "mma.sync.aligned.m16n8k8.row.col.f32.tf32.tf32.f32 "
        "{%0,%1,%2,%3}, {%4,%5,%6,%7}, {%8,%9}, {%0,%1,%2,%3};"
        : "+f"(c[0]), "+f"(c[1]), "+f"(c[2]), "+f"(c[3])
        : "r"(a[0]), "r"(a[1]), "r"(a[2]), "r"(a[3]), "r"(b[0]), "r"(b[1]));
}
__device__ __forceinline__ uint32_t ldsmA_off(int lane, int strideB) {
    const int r = lane & 7, t = lane >> 3;
    return (uint32_t)((r + (t & 1) * 8) * strideB + (t >> 1) * 16);
}
__device__ __forceinline__ uint32_t ldsmB_off(int lane, int strideB) {
    const int r = lane & 7, t = lane >> 3;
    return (uint32_t)((r + (t >> 1) * 8) * strideB + (t & 1) * 16);
}
__device__ __forceinline__ void cpa16(uint32_t s, const void* g) {
    asm volatile("cp.async.cg.shared.global [%0], [%1], 16;" :: "r"(s), "l"(g));
}
#define CP_COMMIT() asm volatile("cp.async.commit_group;" ::: "memory")
#define CP_WAIT0()  asm volatile("cp.async.wait_group 0;" ::: "memory")
#define CP_WAIT1()  asm volatile("cp.async.wait_group 1;" ::: "memory")

// ---------------- tf32 pre-round pass --------------------------------------
__global__ void round_copy(const float4* __restrict__ src, float4* __restrict__ dst, int n4) {
    const int i = blockIdx.x * blockDim.x + threadIdx.x;
    if (i < n4) dst[i] = tf32x4(src[i]);
}

// ===========================================================================
// GEMM: C[M,1024] = A[M,1024] @ W[1024,1024]^T, inputs pre-rounded to tf32
// block 128x128, 128 threads (4 warps, 64x64), BK=16, 3-stage cp.async
// ===========================================================================
#define GROWB 80                       // bytes per smem row (20 floats)
#define GSTG  20480                    // one stage: (A 128x20 + B 128x20) *4B
#define GEMM_SMEM (3 * GSTG)           // 61440

__device__ __forceinline__ void gemm_body(const float* __restrict__ A,
                                          const float* __restrict__ W,
                                          float* __restrict__ C,
                                          int m0, int n0, int round_out)
{
    extern __shared__ float smf[];
    const uint32_t sb = smem_u32(smf);
    const int tid  = threadIdx.x;
    const int lane = tid & 31;
    const int wid  = tid >> 5;
    const int wm   = (wid >> 1) * 64;
    const int wn   = (wid & 1) * 64;

    const uint32_t aoff = ldsmA_off(lane, GROWB);
    const uint32_t boff = ldsmB_off(lane, GROWB);

    const int r  = tid >> 2;       // 0..31 (+32*i)
    const int cq = tid & 3;        // 16B chunk within 64B row data

    auto issue = [&](int s, int buf) {
        const uint32_t as = sb + buf * GSTG;
        const uint32_t bs = as + 128 * GROWB;
        const int k0 = s * 16;
        #pragma unroll
        for (int i = 0; i < 4; i++) {
            const int rr = r + 32 * i;
            cpa16(as + rr * GROWB + cq * 16, A + (size_t)(m0 + rr) * 1024 + k0 + cq * 4);
            cpa16(bs + rr * GROWB + cq * 16, W + (size_t)(n0 + rr) * 1024 + k0 + cq * 4);
        }
        CP_COMMIT();
    };

    issue(0, 0);
    issue(1, 1);

    float acc[4][8][4] = {};

    for (int s = 0; s < 64; s++) {
        CP_WAIT1();
        __syncthreads();
        if (s + 2 < 64) issue(s + 2, (s + 2) % 3); else CP_COMMIT();

        const uint32_t as = sb + (s % 3) * GSTG;
        const uint32_t bs = as + 128 * GROWB;
        #pragma unroll
        for (int ks = 0; ks < 2; ks++) {
            uint32_t a[4][4], b[4][4];
            #pragma unroll
            for (int i = 0; i < 4; i++)
                ldsm4(a[i], as + (wm + 16 * i) * GROWB + ks * 32 + aoff);
            #pragma unroll
            for (int p = 0; p < 4; p++)
                ldsm4(b[p], bs + (wn + 16 * p) * GROWB + ks * 32 + boff);
            #pragma unroll
            for (int i = 0; i < 4; i++)
                #pragma unroll
                for (int j = 0; j < 8; j++)
                    mma_tf32(acc[i][j], a[i], &b[j >> 1][(j & 1) * 2]);
        }
    }

    const int g = lane >> 2, q4 = lane & 3;
    #pragma unroll
    for (int i = 0; i < 4; i++)
        #pragma unroll
        for (int j = 0; j < 8; j++) {
            const int row = m0 + wm + 16 * i + g;
            const int col = n0 + wn + 8 * j + 2 * q4;
            float2 v0, v1;
            if (round_out) {
                v0.x = tf32r(acc[i][j][0]); v0.y = tf32r(acc[i][j][1]);
                v1.x = tf32r(acc[i][j][2]); v1.y = tf32r(acc[i][j][3]);
            } else {
                v0.x = acc[i][j][0]; v0.y = acc[i][j][1];
                v1.x = acc[i][j][2]; v1.y = acc[i][j][3];
            }
            *(float2*)(C + (size_t)row * 1024 + col)       = v0;
            *(float2*)(C + (size_t)(row + 8) * 1024 + col) = v1;
        }
}

__global__ __launch_bounds__(128) void gemm_wo(const float* __restrict__ A,
                                               const float* __restrict__ W,
                                               float* __restrict__ C)
{
    gemm_body(A, W, C, blockIdx.x * 128, blockIdx.y * 128, 0);
}

__global__ __launch_bounds__(128) void gemm_qkv(const float* __restrict__ Q,
                                                const float* __restrict__ K,
                                                const float* __restrict__ V,
                                                const float* __restrict__ WQ,
                                                const float* __restrict__ WK,
                                                const float* __restrict__ WV,
                                                float* __restrict__ gq,
                                                float* __restrict__ gk,
                                                float* __restrict__ gv)
{
    const float* A; const float* W; float* C;
    if (blockIdx.z == 0)      { A = Q; W = WQ; C = gq; }
    else if (blockIdx.z == 1) { A = K; W = WK; C = gk; }
    else                      { A = V; W = WV; C = gv; }
    gemm_body(A, W, C, blockIdx.x * 128, blockIdx.y * 128, 1);
}

// ===========================================================================
// Flash attention: BQ=128 (4 warps x 32 q), Q-frags cached in registers,
// K/V staged 64-wide via 2-deep cp.async, computed in 32-wide halves.
// smem (bytes): Ks[2][64][68]f @0 (34816) | Vs[2][64][72]f @34816 (36864)
//               Ps[128][36]f @71680 (18432)  => 90112 total
// Q staged once into the Ks region (128 rows x 68f = exactly 34816 B).
// ===========================================================================
#define KROWB 272
#define VROWB 288
#define PROWB 144
#define KBUF  17408          // 64*272
#define VBUF  18432          // 64*288
#define VS_B  34816
#define PS_B  71680
#define VS_F  8704
#define PS_F  17920
#define ATTN_SMEM 90112

__global__ __launch_bounds__(128) void attn_tc(const float* __restrict__ qp,
                                               const float* __restrict__ kp,
                                               const float* __restrict__ vp,
                                               float* __restrict__ op)
{
    extern __shared__ float smf[];
    const uint32_t sb  = smem_u32(smf);
    const uint32_t ksb = sb;
    const uint32_t vsb = sb + VS_B;
    const uint32_t psb = sb + PS_B;

    const int tid  = threadIdx.x;
    const int lane = tid & 31;
    const int wid  = tid >> 5;
    const int g    = lane >> 2;
    const int q4   = lane & 3;
    const int qw   = wid * 32;

    const uint32_t aoffQ = ldsmA_off(lane, KROWB);
    const uint32_t boffK = ldsmB_off(lane, KROWB);
    const uint32_t aoffP = ldsmA_off(lane, PROWB);

    const int bh = blockIdx.y;
    const int b  = bh / NHEAD;
    const int h  = bh % NHEAD;
    const int q0 = blockIdx.x * 128;

    const float* qb = qp + (size_t)b * SEQ * DMODEL + h * DHEAD;
    const float* kb = kp + (size_t)b * SEQ * DMODEL + h * DHEAD;
    const float* vb = vp + (size_t)b * SEQ * DMODEL + h * DHEAD;

    const float SC = 0.125f * 1.44269504088896340736f;  // (1/sqrt(dk)) * log2(e)

    // ---- stage Q (128x64) into Ks region, extract fragments, free region --
    #pragma unroll
    for (int i = 0; i < 16; i++) {
        const int c = tid + 128 * i;           // 0..2047
        const int rr = c >> 4, cq = c & 15;
        cpa16(ksb + rr * KROWB + cq * 16, qb + (size_t)(q0 + rr) * DMODEL + cq * 4);
    }
    CP_COMMIT();
    CP_WAIT0();
    __syncthreads();

    uint32_t qf[2][8][4];
    #pragma unroll
    for (int hh = 0; hh < 2; hh++)
        #pragma unroll
        for (int ks = 0; ks < 8; ks++)
            ldsm4(qf[hh][ks], ksb + (qw + 16 * hh) * KROWB + ks * 32 + aoffQ);
    __syncthreads();

    // ---- K/V staging (64 kv rows per tile) --------------------------------
    auto issueKV = [&](int t, int buf) {
        const int kv0 = t * 64;
        #pragma unroll
        for (int i = 0; i < 8; i++) {
            const int c = tid + 128 * i;       // 0..1023
            const int rr = c >> 4, cq = c & 15;
            cpa16(ksb + buf * KBUF + rr * KROWB + cq * 16,
                  kb + (size_t)(kv0 + rr) * DMODEL + cq * 4);
        }
        #pragma unroll
        for (int i = 0; i < 8; i++) {
            const int c = tid + 128 * i;
            const int rr = c >> 4, cq = c & 15;
            cpa16(vsb + buf * VBUF + rr * VROWB + cq * 16,
                  vb + (size_t)(kv0 + rr) * DMODEL + cq * 4);
        }
        CP_COMMIT();
    };

    issueKV(0, 0);
    issueKV(1, 1);

    float m_i[2][2], l_i[2][2], oac[2][8][4];
    #pragma unroll
    for (int hh = 0; hh < 2; hh++) {
        m_i[hh][0] = m_i[hh][1] = -1e30f;
        l_i[hh][0] = l_i[hh][1] = 0.f;
        #pragma unroll
        for (int j = 0; j < 8; j++)
            oac[hh][j][0] = oac[hh][j][1] = oac[hh][j][2] = oac[hh][j][3] = 0.f;
    }

    for (int t = 0; t < 32; t++) {
        CP_WAIT1();
        __syncthreads();
        const int buf = t & 1;
        const uint32_t kbase = ksb + buf * KBUF;
        const int vfbase = VS_F + buf * (VBUF / 4);

        #pragma unroll
        for (int half = 0; half < 2; half++) {
            // ---- S = Q @ K^T over 32 kv -----------------------------------
            float sa[2][4][4] = {};
            #pragma unroll
            for (int ks = 0; ks < 8; ks++) {
                uint32_t bf[2][4];
                ldsm4(bf[0], kbase + (half * 32) * KROWB + ks * 32 + boffK);
                ldsm4(bf[1], kbase + (half * 32 + 16) * KROWB + ks * 32 + boffK);
                #pragma unroll
                for (int hh = 0; hh < 2; hh++)
                    #pragma unroll
                    for (int nt = 0; nt < 4; nt++)
                        mma_tf32(sa[hh][nt], qf[hh][ks], &bf[nt >> 1][(nt & 1) * 2]);
            }

            // ---- online softmax (scale folded into exp2) ------------------
            #pragma unroll
            for (int hh = 0; hh < 2; hh++) {
                float mx0 = -1e30f, mx1 = -1e30f;
                #pragma unroll
                for (int nt = 0; nt < 4; nt++) {
                    mx0 = fmaxf(mx0, fmaxf(sa[hh][nt][0], sa[hh][nt][1]));
                    mx1 = fmaxf(mx1, fmaxf(sa[hh][nt][2], sa[hh][nt][3]));
                }
                mx0 = fmaxf(mx0, __shfl_xor_sync(0xffffffffu, mx0, 1));
                mx0 = fmaxf(mx0, __shfl_xor_sync(0xffffffffu, mx0, 2));
                mx1 = fmaxf(mx1, __shfl_xor_sync(0xffffffffu, mx1, 1));
                mx1 = fmaxf(mx1, __shfl_xor_sync(0xffffffffu, mx1, 2));

                const float mn0 = fmaxf(m_i[hh][0], mx0);
                const float mn1 = fmaxf(m_i[hh][1], mx1);
                const float corr0 = exp2f((m_i[hh][0] - mn0) * SC);
                const float corr1 = exp2f((m_i[hh][1] - mn1) * SC);

                const int r0 = qw + 16 * hh + g;
                float rs0 = 0.f, rs1 = 0.f;
                #pragma unroll
                for (int nt = 0; nt < 4; nt++) {
                    const float p00 = exp2f((sa[hh][nt][0] - mn0) * SC);
                    const float p01 = exp2f((sa[hh][nt][1] - mn0) * SC);
                    const float p10 = exp2f((sa[hh][nt][2] - mn1) * SC);
                    const float p11 = exp2f((sa[hh][nt][3] - mn1) * SC);
                    rs0 += p00 + p01;
                    rs1 += p10 + p11;
                    const int c = 8 * nt + 2 * q4;
                    float2 lo; lo.x = tf32r(p00); lo.y = tf32r(p01);
                    float2 hi; hi.x = tf32r(p10); hi.y = tf32r(p11);
                    *(float2*)&smf[PS_F + r0 * 36 + c]       = lo;
                    *(float2*)&smf[PS_F + (r0 + 8) * 36 + c] = hi;
                }
                rs0 += __shfl_xor_sync(0xffffffffu, rs0, 1);
                rs0 += __shfl_xor_sync(0xffffffffu, rs0, 2);
                rs1 += __shfl_xor_sync(0xffffffffu, rs1, 1);
                rs1 += __shfl_xor_sync(0xffffffffu, rs1, 2);

                l_i[hh][0] = l_i[hh][0] * corr0 + rs0;  m_i[hh][0] = mn0;
                l_i[hh][1] = l_i[hh][1] * corr1 + rs1;  m_i[hh][1] = mn1;

                #pragma unroll
                for (int j = 0; j < 8; j++) {
                    oac[hh][j][0] *= corr0; oac[hh][j][1] *= corr0;
                    oac[hh][j][2] *= corr1; oac[hh][j][3] *= corr1;
                }
            }
            __syncwarp();

            // ---- O += P @ V ----------------------------------------------
            #pragma unroll
            for (int ks2 = 0; ks2 < 4; ks2++) {
                uint32_t af[2][4];
                ldsm4(af[0], psb + qw * PROWB + ks2 * 32 + aoffP);
                ldsm4(af[1], psb + (qw + 16) * PROWB + ks2 * 32 + aoffP);
                uint32_t vf[8][2];
                const int vr = vfbase + (half * 32 + ks2 * 8) * 72;
                #pragma unroll
                for (int j = 0; j < 8; j++) {
                    vf[j][0] = fbits(smf[vr + q4 * 72       + 8 * j + g]);
                    vf[j][1] = fbits(smf[vr + (q4 + 4) * 72 + 8 * j + g]);
                }
                #pragma unroll
                for (int hh = 0; hh < 2; hh++)
                    #pragma unroll
                    for (int j = 0; j < 8; j++)
                        mma_tf32(oac[hh][j], af[hh], vf[j]);
            }
            __syncwarp();
        }

        __syncthreads();
        if (t + 2 < 32) issueKV(t + 2, (t + 2) & 1); else CP_COMMIT();
    }

    // ---- epilogue (tf32-rounded for the WO GEMM) --------------------------
    float* ob = op + (size_t)b * SEQ * DMODEL + h * DHEAD;
    #pragma unroll
    for (int hh = 0; hh < 2; hh++) {
        const float inv0 = 1.0f / l_i[hh][0];
        const float inv1 = 1.0f / l_i[hh][1];
        const int r0 = q0 + qw + 16 * hh + g;
        #pragma unroll
        for (int j = 0; j < 8; j++) {
            const int c = 8 * j + 2 * q4;
            float2 v0, v1;
            v0.x = tf32r(oac[hh][j][0] * inv0); v0.y = tf32r(oac[hh][j][1] * inv0);
            v1.x = tf32r(oac[hh][j][2] * inv1); v1.y = tf32r(oac[hh][j][3] * inv1);
            *(float2*)(ob + (size_t)r0 * DMODEL + c)       = v0;
            *(float2*)(ob + (size_t)(r0 + 8) * DMODEL + c) = v1;
        }
    }
}

// ===========================================================================
extern "C" void kernel_launch(void* const* d_in, const int* in_sizes, int n_in,
                              void* d_out, int out_size)
{
    const float* Q  = (const float*)d_in[0];
    const float* K  = (const float*)d_in[1];
    const float* V  = (const float*)d_in[2];
    const float* WQ = (const float*)d_in[3];
    const float* WK = (const float*)d_in[4];
    const float* WV = (const float*)d_in[5];
    const float* WO = (const float*)d_in[6];
    float* out = (float*)d_out;

    float *gq, *gk, *gv, *go, *qr, *kr, *vr, *wq, *wk, *wv, *wo;
    cudaGetSymbolAddress((void**)&gq, g_q);
    cudaGetSymbolAddress((void**)&gk, g_k);
    cudaGetSymbolAddress((void**)&gv, g_v);
    cudaGetSymbolAddress((void**)&go, g_o);
    cudaGetSymbolAddress((void**)&qr, g_qr);
    cudaGetSymbolAddress((void**)&kr, g_kr);
    cudaGetSymbolAddress((void**)&vr, g_vr);
    cudaGetSymbolAddress((void**)&wq, g_wq);
    cudaGetSymbolAddress((void**)&wk, g_wk);
    cudaGetSymbolAddress((void**)&wv, g_wv);
    cudaGetSymbolAddress((void**)&wo, g_wo);

    static int init = 0;
    if (!init) {
        cudaFuncSetAttribute(attn_tc, cudaFuncAttributeMaxDynamicSharedMemorySize, ATTN_SMEM);
        cudaFuncSetAttribute(gemm_qkv, cudaFuncAttributeMaxDynamicSharedMemorySize, GEMM_SMEM);
        cudaFuncSetAttribute(gemm_wo, cudaFuncAttributeMaxDynamicSharedMemorySize, GEMM_SMEM);
        init = 1;
    }

    // 1) tf32 pre-round of all external inputs
    const int nact4 = MTOT * DMODEL / 4;       // 2097152
    const int nw4   = DMODEL * DMODEL / 4;     // 262144
    round_copy<<<nact4 / 256, 256>>>((const float4*)Q, (float4*)qr, nact4);
    round_copy<<<nact4 / 256, 256>>>((const float4*)K, (float4*)kr, nact4);
    round_copy<<<nact4 / 256, 256>>>((const float4*)V, (float4*)vr, nact4);
    round_copy<<<nw4 / 256, 256>>>((const float4*)WQ, (float4*)wq, nw4);
    round_copy<<<nw4 / 256, 256>>>((const float4*)WK, (float4*)wk, nw4);
    round_copy<<<nw4 / 256, 256>>>((const float4*)WV, (float4*)wv, nw4);
    round_copy<<<nw4 / 256, 256>>>((const float4*)WO, (float4*)wo, nw4);

    // 2) QKV projections (fused z)
    dim3 qkv_grid(MTOT / 128, DMODEL / 128, 3);
    gemm_qkv<<<qkv_grid, 128, GEMM_SMEM>>>(qr, kr, vr, wq, wk, wv, gq, gk, gv);

    // 3) attention
    dim3 attn_grid(SEQ / 128, BATCH * NHEAD);
    attn_tc<<<attn_grid, 128, ATTN_SMEM>>>(gq, gk, gv, go);

    // 4) output projection
    dim3 gemm_grid(MTOT / 128, DMODEL / 128);
    gemm_wo<<<gemm_grid, 128, GEMM_SMEM>>>(go, wo, out);
}

// round 6
// speedup vs baseline: 7.6803x; 1.7371x over previous
#include <cuda_runtime.h>
#include <cuda_fp16.h>
#include <cstdint>

#define BATCH 4
#define SEQ   2048
#define DMODEL 1024
#define NHEAD 16
#define DHEAD 64
#define MTOT  (BATCH * SEQ)   // 8192

// fp16 copies of inputs + fp16 intermediates
__device__ __half g_qh[MTOT * DMODEL];
__device__ __half g_kh[MTOT * DMODEL];
__device__ __half g_vh[MTOT * DMODEL];
__device__ __half g_wq[DMODEL * DMODEL];
__device__ __half g_wk[DMODEL * DMODEL];
__device__ __half g_wv[DMODEL * DMODEL];
__device__ __half g_wo[DMODEL * DMODEL];
__device__ __half g_q[MTOT * DMODEL];
__device__ __half g_k[MTOT * DMODEL];
__device__ __half g_v[MTOT * DMODEL];
__device__ __half g_o[MTOT * DMODEL];

// ---------------- helpers --------------------------------------------------
__device__ __forceinline__ uint32_t smem_u32(const void* p) {
    uint32_t a;
    asm("{ .reg .u64 t; cvta.to.shared.u64 t, %1; cvt.u32.u64 %0, t; }" : "=r"(a) : "l"(p));
    return a;
}
__device__ __forceinline__ void ldsm4(uint32_t r[4], uint32_t addr) {
    asm volatile("ldmatrix.sync.aligned.m8n8.x4.shared.b16 {%0,%1,%2,%3}, [%4];"
                 : "=r"(r[0]), "=r"(r[1]), "=r"(r[2]), "=r"(r[3]) : "r"(addr) : "memory");
}
__device__ __forceinline__ void ldsm4t(uint32_t r[4], uint32_t addr) {
    asm volatile("ldmatrix.sync.aligned.m8n8.x4.trans.shared.b16 {%0,%1,%2,%3}, [%4];"
                 : "=r"(r[0]), "=r"(r[1]), "=r"(r[2]), "=r"(r[3]) : "r"(addr) : "memory");
}
__device__ __forceinline__ void mma_f16(float c[4], const uint32_t a[4], const uint32_t b[2]) {
    asm volatile(
        "mma.sync.aligned.m16n8k16.row.col.f32.f16.f16.f32 "
        "{%0,%1,%2,%3}, {%4,%5,%6,%7}, {%8,%9}, {%0,%1,%2,%3};"
        : "+f"(c[0]), "+f"(c[1]), "+f"(c[2]), "+f"(c[3])
        : "r"(a[0]), "r"(a[1]), "r"(a[2]), "r"(a[3]), "r"(b[0]), "r"(b[1]));
}
// A-type tiles: (m-lo,k-lo)(m-hi,k-lo)(m-lo,k-hi)(m-hi,k-hi)
__device__ __forceinline__ uint32_t ldsmA_off(int lane, int strideB) {
    const int r = lane & 7, t = lane >> 3;
    return (uint32_t)((r + (t & 1) * 8) * strideB + (t >> 1) * 16);
}
// B-type tiles: (n-lo,k-lo)(n-lo,k-hi)(n-hi,k-lo)(n-hi,k-hi)
__device__ __forceinline__ uint32_t ldsmB_off(int lane, int strideB) {
    const int r = lane & 7, t = lane >> 3;
    return (uint32_t)((r + (t >> 1) * 8) * strideB + (t & 1) * 16);
}
__device__ __forceinline__ void cpa16(uint32_t s, const void* g) {
    asm volatile("cp.async.cg.shared.global [%0], [%1], 16;" :: "r"(s), "l"(g));
}
#define CP_COMMIT() asm volatile("cp.async.commit_group;" ::: "memory")
#define CP_WAIT0()  asm volatile("cp.async.wait_group 0;" ::: "memory")
#define CP_WAIT1()  asm volatile("cp.async.wait_group 1;" ::: "memory")

// ---------------- fp16 convert pass ----------------------------------------
__global__ void to_half(const float4* __restrict__ src, __half2* __restrict__ dst, int n4) {
    const int i = blockIdx.x * blockDim.x + threadIdx.x;
    if (i < n4) {
        float4 v = src[i];
        dst[2 * i]     = __floats2half2_rn(v.x, v.y);
        dst[2 * i + 1] = __floats2half2_rn(v.z, v.w);
    }
}

// ===========================================================================
// fp16 GEMM: C[M,1024] = A[M,1024] @ W[1024,1024]^T
// block 128x128, 128 threads (4 warps, 64x64), BK=32, 3-stage cp.async
// ===========================================================================
#define GROWB 80                        // 32 halves (64B) + 16B pad
#define GSTG  20480                     // (128 + 128) rows * 80B
#define GEMM_SMEM (3 * GSTG)            // 61440

template <int ROUND_HALF>
__device__ __forceinline__ void gemm_body(const __half* __restrict__ A,
                                          const __half* __restrict__ W,
                                          __half* __restrict__ Ch,
                                          float* __restrict__ Cf,
                                          int m0, int n0)
{
    extern __shared__ float smf[];
    const uint32_t sb = smem_u32(smf);
    const int tid  = threadIdx.x;
    const int lane = tid & 31;
    const int wid  = tid >> 5;
    const int wm   = (wid >> 1) * 64;
    const int wn   = (wid & 1) * 64;

    const uint32_t aoff = ldsmA_off(lane, GROWB);
    const uint32_t boff = ldsmB_off(lane, GROWB);

    const int r  = tid >> 2;        // 0..31
    const int cq = tid & 3;         // 16B chunk (8 halves)

    auto issue = [&](int s, int buf) {
        const uint32_t as = sb + buf * GSTG;
        const uint32_t bs = as + 128 * GROWB;
        const int k0 = s * 32;
        #pragma unroll
        for (int i = 0; i < 4; i++) {
            const int rr = r + 32 * i;
            cpa16(as + rr * GROWB + cq * 16, A + (size_t)(m0 + rr) * 1024 + k0 + cq * 8);
            cpa16(bs + rr * GROWB + cq * 16, W + (size_t)(n0 + rr) * 1024 + k0 + cq * 8);
        }
        CP_COMMIT();
    };

    issue(0, 0);
    issue(1, 1);

    float acc[4][8][4] = {};

    for (int s = 0; s < 32; s++) {
        CP_WAIT1();
        __syncthreads();
        if (s + 2 < 32) issue(s + 2, (s + 2) % 3); else CP_COMMIT();

        const uint32_t as = sb + (s % 3) * GSTG;
        const uint32_t bs = as + 128 * GROWB;
        #pragma unroll
        for (int ks = 0; ks < 2; ks++) {
            uint32_t a[4][4], b[4][4];
            #pragma unroll
            for (int i = 0; i < 4; i++)
                ldsm4(a[i], as + (wm + 16 * i) * GROWB + ks * 32 + aoff);
            #pragma unroll
            for (int p = 0; p < 4; p++)
                ldsm4(b[p], bs + (wn + 16 * p) * GROWB + ks * 32 + boff);
            #pragma unroll
            for (int i = 0; i < 4; i++)
                #pragma unroll
                for (int j = 0; j < 8; j++)
                    mma_f16(acc[i][j], a[i], &b[j >> 1][(j & 1) * 2]);
        }
    }

    const int g = lane >> 2, q4 = lane & 3;
    #pragma unroll
    for (int i = 0; i < 4; i++)
        #pragma unroll
        for (int j = 0; j < 8; j++) {
            const int row = m0 + wm + 16 * i + g;
            const int col = n0 + wn + 8 * j + 2 * q4;
            if (ROUND_HALF) {
                *(__half2*)(Ch + (size_t)row * 1024 + col) =
                    __floats2half2_rn(acc[i][j][0], acc[i][j][1]);
                *(__half2*)(Ch + (size_t)(row + 8) * 1024 + col) =
                    __floats2half2_rn(acc[i][j][2], acc[i][j][3]);
            } else {
                float2 v0; v0.x = acc[i][j][0]; v0.y = acc[i][j][1];
                float2 v1; v1.x = acc[i][j][2]; v1.y = acc[i][j][3];
                *(float2*)(Cf + (size_t)row * 1024 + col)       = v0;
                *(float2*)(Cf + (size_t)(row + 8) * 1024 + col) = v1;
            }
        }
}

__global__ __launch_bounds__(128) void gemm_wo(const __half* __restrict__ A,
                                               const __half* __restrict__ W,
                                               float* __restrict__ C)
{
    gemm_body<0>(A, W, nullptr, C, blockIdx.x * 128, blockIdx.y * 128);
}

__global__ __launch_bounds__(128) void gemm_qkv(const __half* __restrict__ Q,
                                                const __half* __restrict__ K,
                                                const __half* __restrict__ V,
                                                const __half* __restrict__ WQ,
                                                const __half* __restrict__ WK,
                                                const __half* __restrict__ WV,
                                                __half* __restrict__ gq,
                                                __half* __restrict__ gk,
                                                __half* __restrict__ gv)
{
    const __half* A; const __half* W; __half* C;
    if (blockIdx.z == 0)      { A = Q; W = WQ; C = gq; }
    else if (blockIdx.z == 1) { A = K; W = WK; C = gk; }
    else                      { A = V; W = WV; C = gv; }
    gemm_body<1>(A, W, C, nullptr, blockIdx.x * 128, blockIdx.y * 128);
}

// ===========================================================================
// fp16 flash attention: BQ=128 (4 warps x 32 q), Q-frags cached, BKV=64
// staged 2-deep cp.async, computed in 32-wide halves.
// smem bytes: K[2][64]@144B = 18432 | V[2][64]@144B = 18432 | P[128]@80B = 10240
// ===========================================================================
#define KROWB 144
#define KBUF  9216
#define VS_B  18432
#define PS_B  36864
#define ATTN_SMEM 47104

__global__ __launch_bounds__(128) void attn_tc(const __half* __restrict__ qp,
                                               const __half* __restrict__ kp,
                                               const __half* __restrict__ vp,
                                               __half* __restrict__ op)
{
    extern __shared__ float smf[];
    const uint32_t sb  = smem_u32(smf);
    const uint32_t ksb = sb;
    const uint32_t vsb = sb + VS_B;
    const uint32_t psb = sb + PS_B;
    __half* Ph = (__half*)((char*)smf + PS_B);

    const int tid  = threadIdx.x;
    const int lane = tid & 31;
    const int wid  = tid >> 5;
    const int g    = lane >> 2;
    const int q4   = lane & 3;
    const int qw   = wid * 32;

    const uint32_t aoffQ = ldsmA_off(lane, KROWB);
    const uint32_t boffK = ldsmB_off(lane, KROWB);
    const uint32_t aoffP = ldsmA_off(lane, 80);
    const uint32_t voffT = ldsmA_off(lane, KROWB);   // trans-load tiles for V

    const int bh = blockIdx.y;
    const int b  = bh / NHEAD;
    const int h  = bh % NHEAD;
    const int q0 = blockIdx.x * 128;

    const __half* qb = qp + (size_t)b * SEQ * DMODEL + h * DHEAD;
    const __half* kb = kp + (size_t)b * SEQ * DMODEL + h * DHEAD;
    const __half* vb = vp + (size_t)b * SEQ * DMODEL + h * DHEAD;

    const float SC = 0.125f * 1.44269504088896340736f;   // (1/sqrt(dk))*log2(e)

    // ---- stage Q (128x64 halves) into K region, pull frags, release -------
    #pragma unroll
    for (int i = 0; i < 8; i++) {
        const int c = tid + 128 * i;            // 0..1023
        const int rr = c >> 3, cq = c & 7;
        cpa16(ksb + rr * KROWB + cq * 16, qb + (size_t)(q0 + rr) * DMODEL + cq * 8);
    }
    CP_COMMIT();
    CP_WAIT0();
    __syncthreads();

    uint32_t qf[2][4][4];
    #pragma unroll
    for (int hh = 0; hh < 2; hh++)
        #pragma unroll
        for (int ks = 0; ks < 4; ks++)
            ldsm4(qf[hh][ks], ksb + (qw + 16 * hh) * KROWB + ks * 32 + aoffQ);
    __syncthreads();

    auto issueKV = [&](int t, int buf) {
        const int kv0 = t * 64;
        #pragma unroll
        for (int i = 0; i < 4; i++) {
            const int c = tid + 128 * i;        // 0..511
            const int rr = c >> 3, cq = c & 7;
            cpa16(ksb + buf * KBUF + rr * KROWB + cq * 16,
                  kb + (size_t)(kv0 + rr) * DMODEL + cq * 8);
        }
        #pragma unroll
        for (int i = 0; i < 4; i++) {
            const int c = tid + 128 * i;
            const int rr = c >> 3, cq = c & 7;
            cpa16(vsb + buf * KBUF + rr * KROWB + cq * 16,
                  vb + (size_t)(kv0 + rr) * DMODEL + cq * 8);
        }
        CP_COMMIT();
    };

    issueKV(0, 0);
    issueKV(1, 1);

    float m_i[2][2], l_i[2][2], oac[2][8][4];
    #pragma unroll
    for (int hh = 0; hh < 2; hh++) {
        m_i[hh][0] = m_i[hh][1] = -1e30f;
        l_i[hh][0] = l_i[hh][1] = 0.f;
        #pragma unroll
        for (int j = 0; j < 8; j++)
            oac[hh][j][0] = oac[hh][j][1] = oac[hh][j][2] = oac[hh][j][3] = 0.f;
    }

    for (int t = 0; t < 32; t++) {
        CP_WAIT1();
        __syncthreads();
        const int buf = t & 1;
        const uint32_t kbase = ksb + buf * KBUF;
        const uint32_t vbase = vsb + buf * KBUF;

        #pragma unroll
        for (int half = 0; half < 2; half++) {
            // ---- S = Q @ K^T over 32 kv ----------------------------------
            float sa[2][4][4] = {};
            #pragma unroll
            for (int ks = 0; ks < 4; ks++) {
                uint32_t bf[2][4];
                ldsm4(bf[0], kbase + (half * 32) * KROWB + ks * 32 + boffK);
                ldsm4(bf[1], kbase + (half * 32 + 16) * KROWB + ks * 32 + boffK);
                #pragma unroll
                for (int hh = 0; hh < 2; hh++)
                    #pragma unroll
                    for (int nt = 0; nt < 4; nt++)
                        mma_f16(sa[hh][nt], qf[hh][ks], &bf[nt >> 1][(nt & 1) * 2]);
            }

            // ---- online softmax ------------------------------------------
            #pragma unroll
            for (int hh = 0; hh < 2; hh++) {
                float mx0 = -1e30f, mx1 = -1e30f;
                #pragma unroll
                for (int nt = 0; nt < 4; nt++) {
                    mx0 = fmaxf(mx0, fmaxf(sa[hh][nt][0], sa[hh][nt][1]));
                    mx1 = fmaxf(mx1, fmaxf(sa[hh][nt][2], sa[hh][nt][3]));
                }
                mx0 = fmaxf(mx0, __shfl_xor_sync(0xffffffffu, mx0, 1));
                mx0 = fmaxf(mx0, __shfl_xor_sync(0xffffffffu, mx0, 2));
                mx1 = fmaxf(mx1, __shfl_xor_sync(0xffffffffu, mx1, 1));
                mx1 = fmaxf(mx1, __shfl_xor_sync(0xffffffffu, mx1, 2));

                const float mn0 = fmaxf(m_i[hh][0], mx0);
                const float mn1 = fmaxf(m_i[hh][1], mx1);
                const float corr0 = exp2f((m_i[hh][0] - mn0) * SC);
                const float corr1 = exp2f((m_i[hh][1] - mn1) * SC);

                const int r0 = qw + 16 * hh + g;
                float rs0 = 0.f, rs1 = 0.f;
                #pragma unroll
                for (int nt = 0; nt < 4; nt++) {
                    const float p00 = exp2f((sa[hh][nt][0] - mn0) * SC);
                    const float p01 = exp2f((sa[hh][nt][1] - mn0) * SC);
                    const float p10 = exp2f((sa[hh][nt][2] - mn1) * SC);
                    const float p11 = exp2f((sa[hh][nt][3] - mn1) * SC);
                    rs0 += p00 + p01;
                    rs1 += p10 + p11;
                    const int c = 8 * nt + 2 * q4;
                    *(__half2*)&Ph[r0 * 40 + c]       = __floats2half2_rn(p00, p01);
                    *(__half2*)&Ph[(r0 + 8) * 40 + c] = __floats2half2_rn(p10, p11);
                }
                rs0 += __shfl_xor_sync(0xffffffffu, rs0, 1);
                rs0 += __shfl_xor_sync(0xffffffffu, rs0, 2);
                rs1 += __shfl_xor_sync(0xffffffffu, rs1, 1);
                rs1 += __shfl_xor_sync(0xffffffffu, rs1, 2);

                l_i[hh][0] = l_i[hh][0] * corr0 + rs0;  m_i[hh][0] = mn0;
                l_i[hh][1] = l_i[hh][1] * corr1 + rs1;  m_i[hh][1] = mn1;

                #pragma unroll
                for (int j = 0; j < 8; j++) {
                    oac[hh][j][0] *= corr0; oac[hh][j][1] *= corr0;
                    oac[hh][j][2] *= corr1; oac[hh][j][3] *= corr1;
                }
            }
            __syncwarp();

            // ---- O += P @ V (V via ldmatrix.trans) -----------------------
            #pragma unroll
            for (int ks2 = 0; ks2 < 2; ks2++) {
                uint32_t af[2][4];
                ldsm4(af[0], psb + qw * 80 + ks2 * 32 + aoffP);
                ldsm4(af[1], psb + (qw + 16) * 80 + ks2 * 32 + aoffP);
                #pragma unroll
                for (int j2 = 0; j2 < 4; j2++) {
                    uint32_t vf[4];
                    ldsm4t(vf, vbase + (half * 32 + ks2 * 16) * KROWB + j2 * 32 + voffT);
                    #pragma unroll
                    for (int hh = 0; hh < 2; hh++) {
                        mma_f16(oac[hh][2 * j2],     af[hh], &vf[0]);
                        mma_f16(oac[hh][2 * j2 + 1], af[hh], &vf[2]);
                    }
                }
            }
            __syncwarp();
        }

        __syncthreads();
        if (t + 2 < 32) issueKV(t + 2, (t + 2) & 1); else CP_COMMIT();
    }

    // ---- epilogue (fp16 intermediate for the WO GEMM) ---------------------
    __half* ob = op + (size_t)b * SEQ * DMODEL + h * DHEAD;
    #pragma unroll
    for (int hh = 0; hh < 2; hh++) {
        const float inv0 = 1.0f / l_i[hh][0];
        const float inv1 = 1.0f / l_i[hh][1];
        const int r0 = q0 + qw + 16 * hh + g;
        #pragma unroll
        for (int j = 0; j < 8; j++) {
            const int c = 8 * j + 2 * q4;
            *(__half2*)(ob + (size_t)r0 * DMODEL + c) =
                __floats2half2_rn(oac[hh][j][0] * inv0, oac[hh][j][1] * inv0);
            *(__half2*)(ob + (size_t)(r0 + 8) * DMODEL + c) =
                __floats2half2_rn(oac[hh][j][2] * inv1, oac[hh][j][3] * inv1);
        }
    }
}

// ===========================================================================
extern "C" void kernel_launch(void* const* d_in, const int* in_sizes, int n_in,
                              void* d_out, int out_size)
{
    const float* Q  = (const float*)d_in[0];
    const float* K  = (const float*)d_in[1];
    const float* V  = (const float*)d_in[2];
    const float* WQ = (const float*)d_in[3];
    const float* WK = (const float*)d_in[4];
    const float* WV = (const float*)d_in[5];
    const float* WO = (const float*)d_in[6];
    float* out = (float*)d_out;

    __half *qh, *kh, *vh, *wq, *wk, *wv, *wo, *gq, *gk, *gv, *go;
    cudaGetSymbolAddress((void**)&qh, g_qh);
    cudaGetSymbolAddress((void**)&kh, g_kh);
    cudaGetSymbolAddress((void**)&vh, g_vh);
    cudaGetSymbolAddress((void**)&wq, g_wq);
    cudaGetSymbolAddress((void**)&wk, g_wk);
    cudaGetSymbolAddress((void**)&wv, g_wv);
    cudaGetSymbolAddress((void**)&wo, g_wo);
    cudaGetSymbolAddress((void**)&gq, g_q);
    cudaGetSymbolAddress((void**)&gk, g_k);
    cudaGetSymbolAddress((void**)&gv, g_v);
    cudaGetSymbolAddress((void**)&go, g_o);

    static int init = 0;
    if (!init) {
        cudaFuncSetAttribute(attn_tc, cudaFuncAttributeMaxDynamicSharedMemorySize, ATTN_SMEM);
        cudaFuncSetAttribute(gemm_qkv, cudaFuncAttributeMaxDynamicSharedMemorySize, GEMM_SMEM);
        cudaFuncSetAttribute(gemm_wo, cudaFuncAttributeMaxDynamicSharedMemorySize, GEMM_SMEM);
        init = 1;
    }

    const int nact4 = MTOT * DMODEL / 4;      // 2097152
    const int nw4   = DMODEL * DMODEL / 4;    // 262144
    to_half<<<nact4 / 256, 256>>>((const float4*)Q, (__half2*)qh, nact4);
    to_half<<<nact4 / 256, 256>>>((const float4*)K, (__half2*)kh, nact4);
    to_half<<<nact4 / 256, 256>>>((const float4*)V, (__half2*)vh, nact4);
    to_half<<<nw4 / 256, 256>>>((const float4*)WQ, (__half2*)wq, nw4);
    to_half<<<nw4 / 256, 256>>>((const float4*)WK, (__half2*)wk, nw4);
    to_half<<<nw4 / 256, 256>>>((const float4*)WV, (__half2*)wv, nw4);
    to_half<<<nw4 / 256, 256>>>((const float4*)WO, (__half2*)wo, nw4);

    dim3 qkv_grid(MTOT / 128, DMODEL / 128, 3);
    gemm_qkv<<<qkv_grid, 128, GEMM_SMEM>>>(qh, kh, vh, wq, wk, wv, gq, gk, gv);

    dim3 attn_grid(SEQ / 128, BATCH * NHEAD);
    attn_tc<<<attn_grid, 128, ATTN_SMEM>>>(gq, gk, gv, go);

    dim3 gemm_grid(MTOT / 128, DMODEL / 128);
    gemm_wo<<<gemm_grid, 128, GEMM_SMEM>>>(go, wo, out);
}

// round 8
// speedup vs baseline: 8.4808x; 1.1042x over previous
#include <cuda_runtime.h>
#include <cuda_fp16.h>
#include <cstdint>

#define BATCH 4
#define SEQ   2048
#define DMODEL 1024
#define NHEAD 16
#define DHEAD 64
#define MTOT  (BATCH * SEQ)   // 8192

// fp16 copies of inputs + fp16 intermediates
__device__ __half g_qh[MTOT * DMODEL];
__device__ __half g_kh[MTOT * DMODEL];
__device__ __half g_vh[MTOT * DMODEL];
__device__ __half g_wq[DMODEL * DMODEL];
__device__ __half g_wk[DMODEL * DMODEL];
__device__ __half g_wv[DMODEL * DMODEL];
__device__ __half g_wo[DMODEL * DMODEL];
__device__ __half g_q[MTOT * DMODEL];
__device__ __half g_k[MTOT * DMODEL];
__device__ __half g_v[MTOT * DMODEL];
__device__ __half g_o[MTOT * DMODEL];

// ---------------- helpers --------------------------------------------------
__device__ __forceinline__ uint32_t smem_u32(const void* p) {
    uint32_t a;
    asm("{ .reg .u64 t; cvta.to.shared.u64 t, %1; cvt.u32.u64 %0, t; }" : "=r"(a) : "l"(p));
    return a;
}
__device__ __forceinline__ void ldsm4(uint32_t r[4], uint32_t addr) {
    asm volatile("ldmatrix.sync.aligned.m8n8.x4.shared.b16 {%0,%1,%2,%3}, [%4];"
                 : "=r"(r[0]), "=r"(r[1]), "=r"(r[2]), "=r"(r[3]) : "r"(addr) : "memory");
}
__device__ __forceinline__ void ldsm4t(uint32_t r[4], uint32_t addr) {
    asm volatile("ldmatrix.sync.aligned.m8n8.x4.trans.shared.b16 {%0,%1,%2,%3}, [%4];"
                 : "=r"(r[0]), "=r"(r[1]), "=r"(r[2]), "=r"(r[3]) : "r"(addr) : "memory");
}
__device__ __forceinline__ void mma_f16(float c[4], const uint32_t a[4], const uint32_t b[2]) {
    asm volatile(
        "mma.sync.aligned.m16n8k16.row.col.f32.f16.f16.f32 "
        "{%0,%1,%2,%3}, {%4,%5,%6,%7}, {%8,%9}, {%0,%1,%2,%3};"
        : "+f"(c[0]), "+f"(c[1]), "+f"(c[2]), "+f"(c[3])
        : "r"(a[0]), "r"(a[1]), "r"(a[2]), "r"(a[3]), "r"(b[0]), "r"(b[1]));
}
__device__ __forceinline__ uint32_t ldsmA_off(int lane, int strideB) {
    const int r = lane & 7, t = lane >> 3;
    return (uint32_t)((r + (t & 1) * 8) * strideB + (t >> 1) * 16);
}
__device__ __forceinline__ uint32_t ldsmB_off(int lane, int strideB) {
    const int r = lane & 7, t = lane >> 3;
    return (uint32_t)((r + (t >> 1) * 8) * strideB + (t & 1) * 16);
}
__device__ __forceinline__ void cpa16(uint32_t s, const void* g) {
    asm volatile("cp.async.cg.shared.global [%0], [%1], 16;" :: "r"(s), "l"(g));
}
// pack two fp32 -> f16x2 register (lo = a, hi = b)
__device__ __forceinline__ uint32_t packh2(float a, float b) {
    uint32_t r;
    asm("cvt.rn.f16x2.f32 %0, %1, %2;" : "=r"(r) : "f"(b), "f"(a));
    return r;
}
#define CP_COMMIT() asm volatile("cp.async.commit_group;" ::: "memory")
#define CP_WAIT0()  asm volatile("cp.async.wait_group 0;" ::: "memory")
#define CP_WAIT1()  asm volatile("cp.async.wait_group 1;" ::: "memory")

// ---------------- fp16 convert passes (fused) -------------------------------
__global__ void to_half_act(const float4* __restrict__ Q, const float4* __restrict__ K,
                            const float4* __restrict__ V,
                            __half2* __restrict__ qh, __half2* __restrict__ kh,
                            __half2* __restrict__ vh, int n4) {
    const int i = blockIdx.x * blockDim.x + threadIdx.x;
    if (i >= n4) return;
    const float4* s; __half2* d;
    if (blockIdx.y == 0)      { s = Q; d = qh; }
    else if (blockIdx.y == 1) { s = K; d = kh; }
    else                      { s = V; d = vh; }
    float4 v = s[i];
    d[2 * i]     = __floats2half2_rn(v.x, v.y);
    d[2 * i + 1] = __floats2half2_rn(v.z, v.w);
}
__global__ void to_half_w(const float4* __restrict__ WQ, const float4* __restrict__ WK,
                          const float4* __restrict__ WV, const float4* __restrict__ WO,
                          __half2* __restrict__ wq, __half2* __restrict__ wk,
                          __half2* __restrict__ wv, __half2* __restrict__ wo, int n4) {
    const int i = blockIdx.x * blockDim.x + threadIdx.x;
    if (i >= n4) return;
    const float4* s; __half2* d;
    if (blockIdx.y == 0)      { s = WQ; d = wq; }
    else if (blockIdx.y == 1) { s = WK; d = wk; }
    else if (blockIdx.y == 2) { s = WV; d = wv; }
    else                      { s = WO; d = wo; }
    float4 v = s[i];
    d[2 * i]     = __floats2half2_rn(v.x, v.y);
    d[2 * i + 1] = __floats2half2_rn(v.z, v.w);
}

// ===========================================================================
// fp16 GEMM: C[M,1024] = A[M,1024] @ W[1024,1024]^T
// block 128x128, 128 threads (4 warps, 64x64), BK=32, 3-stage cp.async
// ===========================================================================
#define GROWB 80
#define GSTG  20480
#define GEMM_SMEM (3 * GSTG)

template <int ROUND_HALF>
__device__ __forceinline__ void gemm_body(const __half* __restrict__ A,
                                          const __half* __restrict__ W,
                                          __half* __restrict__ Ch,
                                          float* __restrict__ Cf,
                                          int m0, int n0)
{
    extern __shared__ float smf[];
    const uint32_t sb = smem_u32(smf);
    const int tid  = threadIdx.x;
    const int lane = tid & 31;
    const int wid  = tid >> 5;
    const int wm   = (wid >> 1) * 64;
    const int wn   = (wid & 1) * 64;

    const uint32_t aoff = ldsmA_off(lane, GROWB);
    const uint32_t boff = ldsmB_off(lane, GROWB);

    const int r  = tid >> 2;
    const int cq = tid & 3;

    auto issue = [&](int s, int buf) {
        const uint32_t as = sb + buf * GSTG;
        const uint32_t bs = as + 128 * GROWB;
        const int k0 = s * 32;
        #pragma unroll
        for (int i = 0; i < 4; i++) {
            const int rr = r + 32 * i;
            cpa16(as + rr * GROWB + cq * 16, A + (size_t)(m0 + rr) * 1024 + k0 + cq * 8);
            cpa16(bs + rr * GROWB + cq * 16, W + (size_t)(n0 + rr) * 1024 + k0 + cq * 8);
        }
        CP_COMMIT();
    };

    issue(0, 0);
    issue(1, 1);

    float acc[4][8][4] = {};

    for (int s = 0; s < 32; s++) {
        CP_WAIT1();
        __syncthreads();
        if (s + 2 < 32) issue(s + 2, (s + 2) % 3); else CP_COMMIT();

        const uint32_t as = sb + (s % 3) * GSTG;
        const uint32_t bs = as + 128 * GROWB;
        #pragma unroll
        for (int ks = 0; ks < 2; ks++) {
            uint32_t a[4][4], b[4][4];
            #pragma unroll
            for (int i = 0; i < 4; i++)
                ldsm4(a[i], as + (wm + 16 * i) * GROWB + ks * 32 + aoff);
            #pragma unroll
            for (int p = 0; p < 4; p++)
                ldsm4(b[p], bs + (wn + 16 * p) * GROWB + ks * 32 + boff);
            #pragma unroll
            for (int i = 0; i < 4; i++)
                #pragma unroll
                for (int j = 0; j < 8; j++)
                    mma_f16(acc[i][j], a[i], &b[j >> 1][(j & 1) * 2]);
        }
    }

    const int g = lane >> 2, q4 = lane & 3;
    #pragma unroll
    for (int i = 0; i < 4; i++)
        #pragma unroll
        for (int j = 0; j < 8; j++) {
            const int row = m0 + wm + 16 * i + g;
            const int col = n0 + wn + 8 * j + 2 * q4;
            if (ROUND_HALF) {
                *(__half2*)(Ch + (size_t)row * 1024 + col) =
                    __floats2half2_rn(acc[i][j][0], acc[i][j][1]);
                *(__half2*)(Ch + (size_t)(row + 8) * 1024 + col) =
                    __floats2half2_rn(acc[i][j][2], acc[i][j][3]);
            } else {
                float2 v0; v0.x = acc[i][j][0]; v0.y = acc[i][j][1];
                float2 v1; v1.x = acc[i][j][2]; v1.y = acc[i][j][3];
                *(float2*)(Cf + (size_t)row * 1024 + col)       = v0;
                *(float2*)(Cf + (size_t)(row + 8) * 1024 + col) = v1;
            }
        }
}

__global__ __launch_bounds__(128) void gemm_wo(const __half* __restrict__ A,
                                               const __half* __restrict__ W,
                                               float* __restrict__ C)
{
    gemm_body<0>(A, W, nullptr, C, blockIdx.x * 128, blockIdx.y * 128);
}

__global__ __launch_bounds__(128) void gemm_qkv(const __half* __restrict__ Q,
                                                const __half* __restrict__ K,
                                                const __half* __restrict__ V,
                                                const __half* __restrict__ WQ,
                                                const __half* __restrict__ WK,
                                                const __half* __restrict__ WV,
                                                __half* __restrict__ gq,
                                                __half* __restrict__ gk,
                                                __half* __restrict__ gv)
{
    const __half* A; const __half* W; __half* C;
    if (blockIdx.z == 0)      { A = Q; W = WQ; C = gq; }
    else if (blockIdx.z == 1) { A = K; W = WK; C = gk; }
    else                      { A = V; W = WV; C = gv; }
    gemm_body<1>(A, W, C, nullptr, blockIdx.x * 128, blockIdx.y * 128);
}

// ===========================================================================
// fp16 flash attention: BQ=128 (4 warps x 32 q), Q-frags cached, BKV=64,
// register-resident P (S C-frags repacked as PV A-frags), one softmax / 64kv.
// smem: K[2][64]@144B = 18432 | V[2][64]@144B = 18432  => 36864 B
// ===========================================================================
#define KROWB 144
#define KBUF  9216
#define VS_B  18432
#define ATTN_SMEM 36864

__global__ __launch_bounds__(128) void attn_tc(const __half* __restrict__ qp,
                                               const __half* __restrict__ kp,
                                               const __half* __restrict__ vp,
                                               __half* __restrict__ op)
{
    extern __shared__ float smf[];
    const uint32_t ksb = smem_u32(smf);
    const uint32_t vsb = ksb + VS_B;

    const int tid  = threadIdx.x;
    const int lane = tid & 31;
    const int wid  = tid >> 5;
    const int g    = lane >> 2;
    const int q4   = lane & 3;
    const int qw   = wid * 32;

    const uint32_t aoffQ = ldsmA_off(lane, KROWB);
    const uint32_t boffK = ldsmB_off(lane, KROWB);
    const uint32_t voffT = ldsmA_off(lane, KROWB);

    const int bh = blockIdx.y;
    const int b  = bh / NHEAD;
    const int h  = bh % NHEAD;
    const int q0 = blockIdx.x * 128;

    const __half* qb = qp + (size_t)b * SEQ * DMODEL + h * DHEAD;
    const __half* kb = kp + (size_t)b * SEQ * DMODEL + h * DHEAD;
    const __half* vb = vp + (size_t)b * SEQ * DMODEL + h * DHEAD;

    const float SC = 0.125f * 1.44269504088896340736f;   // (1/sqrt(dk))*log2(e)

    // ---- stage Q (128x64 halves) into K region, pull frags, release -------
    #pragma unroll
    for (int i = 0; i < 8; i++) {
        const int c = tid + 128 * i;
        const int rr = c >> 3, cq = c & 7;
        cpa16(ksb + rr * KROWB + cq * 16, qb + (size_t)(q0 + rr) * DMODEL + cq * 8);
    }
    CP_COMMIT();
    CP_WAIT0();
    __syncthreads();

    uint32_t qf[2][4][4];
    #pragma unroll
    for (int hh = 0; hh < 2; hh++)
        #pragma unroll
        for (int ks = 0; ks < 4; ks++)
            ldsm4(qf[hh][ks], ksb + (qw + 16 * hh) * KROWB + ks * 32 + aoffQ);
    __syncthreads();

    auto issueKV = [&](int t, int buf) {
        const int kv0 = t * 64;
        #pragma unroll
        for (int i = 0; i < 4; i++) {
            const int c = tid + 128 * i;
            const int rr = c >> 3, cq = c & 7;
            cpa16(ksb + buf * KBUF + rr * KROWB + cq * 16,
                  kb + (size_t)(kv0 + rr) * DMODEL + cq * 8);
        }
        #pragma unroll
        for (int i = 0; i < 4; i++) {
            const int c = tid + 128 * i;
            const int rr = c >> 3, cq = c & 7;
            cpa16(vsb + buf * KBUF + rr * KROWB + cq * 16,
                  vb + (size_t)(kv0 + rr) * DMODEL + cq * 8);
        }
        CP_COMMIT();
    };

    issueKV(0, 0);
    issueKV(1, 1);

    float m_i[2][2], l_i[2][2], oac[2][8][4];
    #pragma unroll
    for (int hh = 0; hh < 2; hh++) {
        m_i[hh][0] = m_i[hh][1] = -1e30f;
        l_i[hh][0] = l_i[hh][1] = 0.f;
        #pragma unroll
        for (int j = 0; j < 8; j++)
            oac[hh][j][0] = oac[hh][j][1] = oac[hh][j][2] = oac[hh][j][3] = 0.f;
    }

    for (int t = 0; t < 32; t++) {
        CP_WAIT1();
        __syncthreads();
        const int buf = t & 1;
        const uint32_t kbase = ksb + buf * KBUF;
        const uint32_t vbase = vsb + buf * KBUF;

        // ---- S = Q @ K^T over full 64 kv ---------------------------------
        float sa[2][8][4] = {};
        #pragma unroll
        for (int ks = 0; ks < 4; ks++) {
            uint32_t bf[4][4];
            #pragma unroll
            for (int p = 0; p < 4; p++)
                ldsm4(bf[p], kbase + 16 * p * KROWB + ks * 32 + boffK);
            #pragma unroll
            for (int hh = 0; hh < 2; hh++)
                #pragma unroll
                for (int nt = 0; nt < 8; nt++)
                    mma_f16(sa[hh][nt], qf[hh][ks], &bf[nt >> 1][(nt & 1) * 2]);
        }

        // ---- one online-softmax pass over 64 columns ---------------------
        uint32_t pf[2][4][4];
        #pragma unroll
        for (int hh = 0; hh < 2; hh++) {
            float mx0 = -1e30f, mx1 = -1e30f;
            #pragma unroll
            for (int nt = 0; nt < 8; nt++) {
                mx0 = fmaxf(mx0, fmaxf(sa[hh][nt][0], sa[hh][nt][1]));
                mx1 = fmaxf(mx1, fmaxf(sa[hh][nt][2], sa[hh][nt][3]));
            }
            mx0 = fmaxf(mx0, __shfl_xor_sync(0xffffffffu, mx0, 1));
            mx0 = fmaxf(mx0, __shfl_xor_sync(0xffffffffu, mx0, 2));
            mx1 = fmaxf(mx1, __shfl_xor_sync(0xffffffffu, mx1, 1));
            mx1 = fmaxf(mx1, __shfl_xor_sync(0xffffffffu, mx1, 2));

            const float mn0 = fmaxf(m_i[hh][0], mx0);
            const float mn1 = fmaxf(m_i[hh][1], mx1);
            const float corr0 = exp2f((m_i[hh][0] - mn0) * SC);
            const float corr1 = exp2f((m_i[hh][1] - mn1) * SC);

            float rs0 = 0.f, rs1 = 0.f;
            #pragma unroll
            for (int nt = 0; nt < 8; nt++) {
                const float p0 = exp2f((sa[hh][nt][0] - mn0) * SC);
                const float p1 = exp2f((sa[hh][nt][1] - mn0) * SC);
                const float p2 = exp2f((sa[hh][nt][2] - mn1) * SC);
                const float p3 = exp2f((sa[hh][nt][3] - mn1) * SC);
                rs0 += p0 + p1;
                rs1 += p2 + p3;
                sa[hh][nt][0] = p0; sa[hh][nt][1] = p1;
                sa[hh][nt][2] = p2; sa[hh][nt][3] = p3;
            }
            rs0 += __shfl_xor_sync(0xffffffffu, rs0, 1);
            rs0 += __shfl_xor_sync(0xffffffffu, rs0, 2);
            rs1 += __shfl_xor_sync(0xffffffffu, rs1, 1);
            rs1 += __shfl_xor_sync(0xffffffffu, rs1, 2);

            l_i[hh][0] = l_i[hh][0] * corr0 + rs0;  m_i[hh][0] = mn0;
            l_i[hh][1] = l_i[hh][1] * corr1 + rs1;  m_i[hh][1] = mn1;

            #pragma unroll
            for (int j = 0; j < 8; j++) {
                oac[hh][j][0] *= corr0; oac[hh][j][1] *= corr0;
                oac[hh][j][2] *= corr1; oac[hh][j][3] *= corr1;
            }

            // pack P: S C-frags (tiles 2c, 2c+1) -> PV A-frag for k-chunk c
            #pragma unroll
            for (int c = 0; c < 4; c++) {
                pf[hh][c][0] = packh2(sa[hh][2 * c][0],     sa[hh][2 * c][1]);
                pf[hh][c][1] = packh2(sa[hh][2 * c][2],     sa[hh][2 * c][3]);
                pf[hh][c][2] = packh2(sa[hh][2 * c + 1][0], sa[hh][2 * c + 1][1]);
                pf[hh][c][3] = packh2(sa[hh][2 * c + 1][2], sa[hh][2 * c + 1][3]);
            }
        }

        // ---- O += P @ V (V via ldmatrix.trans), k = 64 in 4 chunks -------
        #pragma unroll
        for (int c = 0; c < 4; c++) {
            #pragma unroll
            for (int j2 = 0; j2 < 4; j2++) {
                uint32_t vf[4];
                ldsm4t(vf, vbase + 16 * c * KROWB + j2 * 32 + voffT);
                #pragma unroll
                for (int hh = 0; hh < 2; hh++) {
                    mma_f16(oac[hh][2 * j2],     pf[hh][c], &vf[0]);
                    mma_f16(oac[hh][2 * j2 + 1], pf[hh][c], &vf[2]);
                }
            }
        }

        __syncthreads();
        if (t + 2 < 32) issueKV(t + 2, (t + 2) & 1); else CP_COMMIT();
    }

    // ---- epilogue (fp16 intermediate for the WO GEMM) ---------------------
    __half* ob = op + (size_t)b * SEQ * DMODEL + h * DHEAD;
    #pragma unroll
    for (int hh = 0; hh < 2; hh++) {
        const float inv0 = 1.0f / l_i[hh][0];
        const float inv1 = 1.0f / l_i[hh][1];
        const int r0 = q0 + qw + 16 * hh + g;
        #pragma unroll
        for (int j = 0; j < 8; j++) {
            const int c = 8 * j + 2 * q4;
            *(__half2*)(ob + (size_t)r0 * DMODEL + c) =
                __floats2half2_rn(oac[hh][j][0] * inv0, oac[hh][j][1] * inv0);
            *(__half2*)(ob + (size_t)(r0 + 8) * DMODEL + c) =
                __floats2half2_rn(oac[hh][j][2] * inv1, oac[hh][j][3] * inv1);
        }
    }
}

// ===========================================================================
extern "C" void kernel_launch(void* const* d_in, const int* in_sizes, int n_in,
                              void* d_out, int out_size)
{
    const float* Q  = (const float*)d_in[0];
    const float* K  = (const float*)d_in[1];
    const float* V  = (const float*)d_in[2];
    const float* WQ = (const float*)d_in[3];
    const float* WK = (const float*)d_in[4];
    const float* WV = (const float*)d_in[5];
    const float* WO = (const float*)d_in[6];
    float* out = (float*)d_out;

    __half *qh, *kh, *vh, *wq, *wk, *wv, *wo, *gq, *gk, *gv, *go;
    cudaGetSymbolAddress((void**)&qh, g_qh);
    cudaGetSymbolAddress((void**)&kh, g_kh);
    cudaGetSymbolAddress((void**)&vh, g_vh);
    cudaGetSymbolAddress((void**)&wq, g_wq);
    cudaGetSymbolAddress((void**)&wk, g_wk);
    cudaGetSymbolAddress((void**)&wv, g_wv);
    cudaGetSymbolAddress((void**)&wo, g_wo);
    cudaGetSymbolAddress((void**)&gq, g_q);
    cudaGetSymbolAddress((void**)&gk, g_k);
    cudaGetSymbolAddress((void**)&gv, g_v);
    cudaGetSymbolAddress((void**)&go, g_o);

    static int init = 0;
    if (!init) {
        cudaFuncSetAttribute(attn_tc, cudaFuncAttributeMaxDynamicSharedMemorySize, ATTN_SMEM);
        cudaFuncSetAttribute(gemm_qkv, cudaFuncAttributeMaxDynamicSharedMemorySize, GEMM_SMEM);
        cudaFuncSetAttribute(gemm_wo, cudaFuncAttributeMaxDynamicSharedMemorySize, GEMM_SMEM);
        init = 1;
    }

    const int nact4 = MTOT * DMODEL / 4;      // 2097152
    const int nw4   = DMODEL * DMODEL / 4;    // 262144
    {
        dim3 grid(nact4 / 256, 3);
        to_half_act<<<grid, 256>>>((const float4*)Q, (const float4*)K, (const float4*)V,
                                   (__half2*)qh, (__half2*)kh, (__half2*)vh, nact4);
    }
    {
        dim3 grid(nw4 / 256, 4);
        to_half_w<<<grid, 256>>>((const float4*)WQ, (const float4*)WK,
                                 (const float4*)WV, (const float4*)WO,
                                 (__half2*)wq, (__half2*)wk, (__half2*)wv, (__half2*)wo, nw4);
    }

    dim3 qkv_grid(MTOT / 128, DMODEL / 128, 3);
    gemm_qkv<<<qkv_grid, 128, GEMM_SMEM>>>(qh, kh, vh, wq, wk, wv, gq, gk, gv);

    dim3 attn_grid(SEQ / 128, BATCH * NHEAD);
    attn_tc<<<attn_grid, 128, ATTN_SMEM>>>(gq, gk, gv, go);

    dim3 gemm_grid(MTOT / 128, DMODEL / 128);
    gemm_wo<<<gemm_grid, 128, GEMM_SMEM>>>(go, wo, out);
}